// round 13
// baseline (speedup 1.0000x reference)
#include <cuda_runtime.h>
#include <cuda_bf16.h>
#include <cstdint>
#include <math.h>

#define B_   2
#define H_   16
#define N_   2048
#define D_   64
#define C_   1024
#define BH_  (B_*H_)

// bf16 hi/lo scratch
__device__ __nv_bfloat16 g_xh[4096*1024], g_xl[4096*1024];     // X split, [row][k]
__device__ __nv_bfloat16 g_wqh[3072*1024], g_wql[3072*1024];   // Wqkv^T split, [n][k]
__device__ __nv_bfloat16 g_woh[1024*1024], g_wol[1024*1024];   // Wout^T split, [n][k]
__device__ __nv_bfloat16 g_aoh[4096*1024], g_aol[4096*1024];   // attn out split, [row][k]
// attention operands (written by gemm_qkv_mma epilogue)
__device__ __nv_bfloat16 g_qh2[BH_*N_*D_], g_ql2[BH_*N_*D_];   // [bh][tok][64], *log2e/32
__device__ __nv_bfloat16 g_kh2[BH_*N_*D_], g_kl2[BH_*N_*D_];   // [bh][tok][64]
__device__ __nv_bfloat16 g_vth[BH_*N_*D_], g_vtl[BH_*N_*D_];   // [bh][d][tok]  (transposed)

// ---- helpers ----
__device__ __forceinline__ uint32_t smem_u32(const void* p) {
    uint32_t a;
    asm("{ .reg .u64 t; cvta.to.shared.u64 t, %1; cvt.u32.u64 %0, t; }" : "=r"(a) : "l"(p));
    return a;
}
__device__ __forceinline__ void ldmx4(uint32_t* r, uint32_t addr) {
    asm volatile("ldmatrix.sync.aligned.m8n8.x4.shared.b16 {%0,%1,%2,%3}, [%4];"
                 : "=r"(r[0]), "=r"(r[1]), "=r"(r[2]), "=r"(r[3]) : "r"(addr));
}
__device__ __forceinline__ void mma_bf16(float* d, const uint32_t* a, uint32_t b0, uint32_t b1) {
    asm volatile("mma.sync.aligned.m16n8k16.row.col.f32.bf16.bf16.f32 "
                 "{%0,%1,%2,%3}, {%4,%5,%6,%7}, {%8,%9}, {%0,%1,%2,%3};"
                 : "+f"(d[0]), "+f"(d[1]), "+f"(d[2]), "+f"(d[3])
                 : "r"(a[0]), "r"(a[1]), "r"(a[2]), "r"(a[3]), "r"(b0), "r"(b1));
}
__device__ __forceinline__ void bsplit(float v, __nv_bfloat16& h, __nv_bfloat16& l) {
    h = __float2bfloat16_rn(v);
    l = __float2bfloat16_rn(v - __bfloat162float(h));
}
__device__ __forceinline__ uint32_t pack_bf2(__nv_bfloat16 lo, __nv_bfloat16 hi) {
    __nv_bfloat162 p; p.x = lo; p.y = hi;
    return *(uint32_t*)&p;
}
__device__ __forceinline__ void cp16(uint32_t saddr, const void* gaddr) {
    asm volatile("cp.async.cg.shared.global [%0], [%1], 16;" :: "r"(saddr), "l"(gaddr));
}
#define CP_COMMIT() asm volatile("cp.async.commit_group;" ::: "memory")
#define CP_WAIT(n)  asm volatile("cp.async.wait_group %0;" :: "n"(n) : "memory")

// ===========================================================================
// Splitters
// ===========================================================================
__global__ void __launch_bounds__(256) split_x(const float* __restrict__ X) {
    int i = blockIdx.x*256 + threadIdx.x;
    float4 v = ((const float4*)X)[i];
    __nv_bfloat16 h[4], l[4];
    bsplit(v.x, h[0], l[0]); bsplit(v.y, h[1], l[1]);
    bsplit(v.z, h[2], l[2]); bsplit(v.w, h[3], l[3]);
    *(uint2*)&g_xh[(size_t)i*4] = *(uint2*)h;
    *(uint2*)&g_xl[(size_t)i*4] = *(uint2*)l;
}

__global__ void __launch_bounds__(256) split_wT(const float* __restrict__ W, int Nn, int which) {
    __shared__ float sm[32][33];
    const int tx = threadIdx.x, ty = threadIdx.y;
    const int nx = blockIdx.x*32, kx = blockIdx.y*32;
    #pragma unroll
    for (int i = 0; i < 4; i++)
        sm[ty + i*8][tx] = W[(size_t)(kx + ty + i*8)*Nn + nx + tx];
    __syncthreads();
    __nv_bfloat16* Th = which ? g_woh : g_wqh;
    __nv_bfloat16* Tl = which ? g_wol : g_wql;
    #pragma unroll
    for (int i = 0; i < 4; i++) {
        float v = sm[tx][ty + i*8];
        __nv_bfloat16 h, l; bsplit(v, h, l);
        size_t o = (size_t)(nx + ty + i*8)*1024 + kx + tx;
        Th[o] = h; Tl[o] = l;
    }
}

// ===========================================================================
// bf16 3-pass mma GEMM, 3-stage cp.async pipeline with k32 stages.
// CTA 128x128, 8 warps (2m x 4n), warp 64x32.
// Stage = 32KB: Ah@0 Al@8192 Bh@16384 Bl@24576, each [kcb0..3][128][16B].
// 32 chunks of k32. Dynamic smem 96KB -> 2 CTA/SM.
// ===========================================================================
#define GSTAGE 32768
#define GEMM_SMEM (3*GSTAGE)

struct MmaCtx {
    float acc[4][4][4];
    uint32_t sb;
    int offA, offB;
    int wm, wn, lane;
    const char *gAh, *gAl, *gBh, *gBl;   // per-thread row base pointers
    uint32_t dA0, dA1;                   // smem dst cell offsets (u=0,1)
    int gk0, gk1;                        // global byte offsets within chunk (u=0,1)
};

__device__ __forceinline__ void mma_init(MmaCtx& c, void* smem,
        const __nv_bfloat16* Ah, const __nv_bfloat16* Al,
        const __nv_bfloat16* Bh, const __nv_bfloat16* Bl,
        int bm, int bn) {
    const int t = threadIdx.x, l = t & 31, w = t >> 5;
    c.lane = l; c.wm = w & 1; c.wn = w >> 1;
    c.sb = smem_u32(smem);
    #pragma unroll
    for (int a = 0; a < 4; a++)
        #pragma unroll
        for (int b = 0; b < 4; b++)
            #pragma unroll
            for (int d = 0; d < 4; d++) c.acc[a][b][d] = 0.f;

    const int arow = t & 127, akc0 = (t >> 7) * 2;
    c.gAh = (const char*)(Ah + (size_t)(bm*128 + arow)*1024);
    c.gAl = (const char*)(Al + (size_t)(bm*128 + arow)*1024);
    c.gBh = (const char*)(Bh + (size_t)(bn*128 + arow)*1024);
    c.gBl = (const char*)(Bl + (size_t)(bn*128 + arow)*1024);
    c.dA0 = (uint32_t)(((akc0+0)*128 + arow)*16);
    c.dA1 = (uint32_t)(((akc0+1)*128 + arow)*16);
    c.gk0 = (akc0+0)*16;
    c.gk1 = (akc0+1)*16;

    const int rowA = c.wm*64 + ((l>>3)&1)*8 + (l&7), kcA = l>>4;
    c.offA = (kcA*128 + rowA)*16;
    const int nB = c.wn*32 + (l&7) + (l>>4)*8, kcB = (l>>3)&1;
    c.offB = (kcB*128 + nB)*16;
}

__device__ __forceinline__ void mma_issue(MmaCtx& c, int j, int slot) {
    const uint32_t S = c.sb + slot*GSTAGE;
    const size_t go = (size_t)j * 64;      // 32 k-elems * 2B per chunk
    cp16(S + c.dA0,          c.gAh + go + c.gk0);
    cp16(S + c.dA1,          c.gAh + go + c.gk1);
    cp16(S + 8192 + c.dA0,   c.gAl + go + c.gk0);
    cp16(S + 8192 + c.dA1,   c.gAl + go + c.gk1);
    cp16(S + 16384 + c.dA0,  c.gBh + go + c.gk0);
    cp16(S + 16384 + c.dA1,  c.gBh + go + c.gk1);
    cp16(S + 24576 + c.dA0,  c.gBl + go + c.gk0);
    cp16(S + 24576 + c.dA1,  c.gBl + go + c.gk1);
    CP_COMMIT();
}

__device__ __forceinline__ void mma_compute(MmaCtx& c, int slot) {
    const uint32_t S = c.sb + slot*GSTAGE;
    #pragma unroll
    for (int h = 0; h < 2; h++) {
        const uint32_t hA = S + c.offA + h*4096;
        const uint32_t hB = S + 16384 + c.offB + h*4096;
        uint32_t Ah_[4][4], Al_[4][4];
        #pragma unroll
        for (int mt = 0; mt < 4; mt++) {
            ldmx4(Ah_[mt], hA + mt*256);
            ldmx4(Al_[mt], hA + 8192 + mt*256);
        }
        #pragma unroll
        for (int ntp = 0; ntp < 2; ntp++) {
            uint32_t bh[4], bl[4];
            ldmx4(bh, hB + ntp*256);
            ldmx4(bl, hB + 8192 + ntp*256);
            #pragma unroll
            for (int n2 = 0; n2 < 2; n2++) {
                const int nt = ntp*2 + n2;
                #pragma unroll
                for (int mt = 0; mt < 4; mt++) {
                    mma_bf16(c.acc[mt][nt], Ah_[mt], bh[n2*2], bh[n2*2+1]);
                    mma_bf16(c.acc[mt][nt], Ah_[mt], bl[n2*2], bl[n2*2+1]);
                    mma_bf16(c.acc[mt][nt], Al_[mt], bh[n2*2], bh[n2*2+1]);
                }
            }
        }
    }
}

#define MMA_MAIN(c)                                        \
    mma_issue(c, 0, 0); mma_issue(c, 1, 1);                \
    for (int j = 0; j < 32; j++) {                         \
        CP_WAIT(1);                                        \
        __syncthreads();                                   \
        if (j + 2 < 32) mma_issue(c, j+2, (j+2)%3);        \
        mma_compute(c, j%3);                               \
    }

__global__ void __launch_bounds__(256, 2) gemm_qkv_mma() {
    extern __shared__ __align__(16) char smem[];
    MmaCtx c;
    const int bn = blockIdx.x, bm = blockIdx.y;
    mma_init(c, smem, g_xh, g_xl, g_wqh, g_wql, bm, bn);
    MMA_MAIN(c);

    const int sel = bn >> 3;
    const float sc = (sel == 0) ? 0.03125f * 1.4426950408889634f : 1.0f;
    #pragma unroll
    for (int mt = 0; mt < 4; mt++) {
        const int row0 = bm*128 + c.wm*64 + mt*16 + (c.lane >> 2);
        #pragma unroll
        for (int nt = 0; nt < 4; nt++) {
            const int col = (bn & 7)*128 + c.wn*32 + nt*8 + (c.lane & 3)*2;
            const int h = col >> 6, d = col & 63;
            #pragma unroll
            for (int half = 0; half < 2; half++) {
                const int r = row0 + half*8;
                const int bb = r >> 11, nr = r & 2047;
                const int bh_ = bb*H_ + h;
                float f0 = c.acc[mt][nt][half*2+0]*sc;
                float f1 = c.acc[mt][nt][half*2+1]*sc;
                __nv_bfloat16 h0,l0,h1,l1;
                bsplit(f0, h0, l0); bsplit(f1, h1, l1);
                if (sel == 2) {
                    size_t o = ((size_t)bh_*D_ + d)*N_ + nr;
                    g_vth[o] = h0; g_vtl[o] = l0;
                    g_vth[o + N_] = h1; g_vtl[o + N_] = l1;
                } else {
                    size_t o = ((size_t)bh_*N_ + nr)*D_ + d;
                    __nv_bfloat16* Dh = sel ? g_kh2 : g_qh2;
                    __nv_bfloat16* Dl = sel ? g_kl2 : g_ql2;
                    *(uint32_t*)&Dh[o] = pack_bf2(h0, h1);
                    *(uint32_t*)&Dl[o] = pack_bf2(l0, l1);
                }
            }
        }
    }
}

__global__ void __launch_bounds__(256, 2) gemm_out_mma(const float* __restrict__ bias,
                                                       float* __restrict__ out) {
    extern __shared__ __align__(16) char smem[];
    MmaCtx c;
    const int bn = blockIdx.x, bm = blockIdx.y;
    mma_init(c, smem, g_aoh, g_aol, g_woh, g_wol, bm, bn);
    MMA_MAIN(c);

    #pragma unroll
    for (int mt = 0; mt < 4; mt++) {
        const int row0 = bm*128 + c.wm*64 + mt*16 + (c.lane >> 2);
        #pragma unroll
        for (int nt = 0; nt < 4; nt++) {
            const int col = bn*128 + c.wn*32 + nt*8 + (c.lane & 3)*2;
            const float2 bv = *(const float2*)&bias[col];
            #pragma unroll
            for (int half = 0; half < 2; half++) {
                const size_t r = (size_t)(row0 + half*8);
                float2 o = make_float2(c.acc[mt][nt][half*2+0] + bv.x,
                                       c.acc[mt][nt][half*2+1] + bv.y);
                *(float2*)&out[r*C_ + col] = o;
            }
        }
    }
}

// ===========================================================================
// Attention on mma.sync, cp.async double-buffered K/V (unchanged from R12).
// smem: sQ 32KB | stage0 KV 32KB | stage1 KV 32KB  = 96KB dynamic.
// ===========================================================================
#define ATTN_SMEM 98304

__global__ void __launch_bounds__(256) attn_mma() {
    extern __shared__ __align__(16) char smem[];
    char* sQ = smem;
    const uint32_t sbQ = smem_u32(sQ);
    const uint32_t sbKV = sbQ + 32768;

    const int t = threadIdx.x, l = t & 31, w = t >> 5;
    const int it = blockIdx.x, bh = blockIdx.y;
    const size_t base = (size_t)bh * (N_*D_);

    {
        const int row = t & 127;
        const int kcb0 = (t >> 7) * 4;
        const uint4* gh = (const uint4*)(g_qh2 + base + (size_t)(it*128 + row)*D_);
        const uint4* gl = (const uint4*)(g_ql2 + base + (size_t)(it*128 + row)*D_);
        #pragma unroll
        for (int u = 0; u < 4; u++) {
            const int kcb = kcb0 + u;
            *(uint4*)(sQ + (kcb*128 + row)*16)         = gh[kcb];
            *(uint4*)(sQ + 16384 + (kcb*128 + row)*16) = gl[kcb];
        }
    }

    const int rowQ = w*16 + ((l>>3)&1)*8 + (l&7);
    const int offQ = rowQ*16 + (l>>4)*2048;
    const int offB = (((l>>3)&1)*64 + (l&7) + (l>>4)*8)*16;

    const int jrow = t & 63;
    const int kcb2 = (t >> 6) * 2;
    const char* gKh = (const char*)(g_kh2 + base + (size_t)jrow*D_) + kcb2*16;
    const char* gKl = (const char*)(g_kl2 + base + (size_t)jrow*D_) + kcb2*16;
    const char* gVh = (const char*)(g_vth + base + (size_t)jrow*N_) + kcb2*16;
    const char* gVl = (const char*)(g_vtl + base + (size_t)jrow*N_) + kcb2*16;
    const uint32_t dK = (uint32_t)((kcb2*64 + jrow)*16);

    auto kv_issue = [&](int jt, int slot) {
        const uint32_t S = sbKV + slot*32768 + dK;
        const size_t koff = (size_t)jt * 64 * D_ * 2;
        const size_t voff = (size_t)jt * 64 * 2;
        #pragma unroll
        for (int u = 0; u < 2; u++) {
            cp16(S + u*1024,          gKh + koff + u*16);
            cp16(S + 8192 + u*1024,   gKl + koff + u*16);
            cp16(S + 16384 + u*1024,  gVh + voff + u*16);
            cp16(S + 24576 + u*1024,  gVl + voff + u*16);
        }
        CP_COMMIT();
    };

    float oacc[8][4];
    #pragma unroll
    for (int nt = 0; nt < 8; nt++)
        #pragma unroll
        for (int d = 0; d < 4; d++) oacc[nt][d] = 0.f;
    float lrun0 = 0.f, lrun1 = 0.f;

    const int row_glob0 = it*128 + w*16 + (l>>2);

    kv_issue(0, 0);

    for (int jt = 0; jt < 32; jt++) {
        CP_WAIT(0);
        __syncthreads();
        if (jt + 1 < 32) kv_issue(jt+1, (jt+1)&1);

        const uint32_t sbK = sbKV + (jt&1)*32768;
        const uint32_t sbV = sbK + 16384;

        float sacc[8][4];
        #pragma unroll
        for (int nt = 0; nt < 8; nt++)
            #pragma unroll
            for (int d = 0; d < 4; d++) sacc[nt][d] = 0.f;

        #pragma unroll
        for (int kc = 0; kc < 4; kc++) {
            uint32_t qh[4], ql[4];
            ldmx4(qh, sbQ + offQ + kc*4096);
            ldmx4(ql, sbQ + 16384 + offQ + kc*4096);
            #pragma unroll
            for (int np = 0; np < 4; np++) {
                uint32_t kbh[4], kbl[4];
                ldmx4(kbh, sbK + kc*2048 + offB + np*256);
                ldmx4(kbl, sbK + 8192 + kc*2048 + offB + np*256);
                #pragma unroll
                for (int n2 = 0; n2 < 2; n2++) {
                    const int nt = np*2 + n2;
                    mma_bf16(sacc[nt], qh, kbh[n2*2], kbh[n2*2+1]);
                    mma_bf16(sacc[nt], qh, kbl[n2*2], kbl[n2*2+1]);
                    mma_bf16(sacc[nt], ql, kbh[n2*2], kbh[n2*2+1]);
                }
            }
        }

        uint32_t pah[4][4], pal[4][4];
        #pragma unroll
        for (int nt = 0; nt < 8; nt++) {
            const int colb = jt*64 + nt*8 + (l & 3)*2;
            const int del0 = row_glob0 - colb;
            const int dels[4] = {del0, del0 - 1, del0 + 8, del0 + 7};
            float p[4];
            #pragma unroll
            for (int e = 0; e < 4; e++) {
                const int de = dels[e];
                const bool msk = (de >= 0) && ((de & 31) == 0);
                p[e] = msk ? 0.f : exp2f(sacc[nt][e]);
            }
            lrun0 += p[0] + p[1];
            lrun1 += p[2] + p[3];
            __nv_bfloat16 h0,l0,h1,l1,h2,l2,h3,l3;
            bsplit(p[0], h0, l0); bsplit(p[1], h1, l1);
            bsplit(p[2], h2, l2); bsplit(p[3], h3, l3);
            const int kk = nt >> 1, sl = (nt & 1)*2;
            pah[kk][sl+0] = pack_bf2(h0, h1);
            pah[kk][sl+1] = pack_bf2(h2, h3);
            pal[kk][sl+0] = pack_bf2(l0, l1);
            pal[kk][sl+1] = pack_bf2(l2, l3);
        }

        #pragma unroll
        for (int kk = 0; kk < 4; kk++) {
            #pragma unroll
            for (int np = 0; np < 4; np++) {
                uint32_t vbh[4], vbl[4];
                ldmx4(vbh, sbV + kk*2048 + offB + np*256);
                ldmx4(vbl, sbV + 8192 + kk*2048 + offB + np*256);
                #pragma unroll
                for (int n2 = 0; n2 < 2; n2++) {
                    const int nt = np*2 + n2;
                    mma_bf16(oacc[nt], pah[kk], vbh[n2*2], vbh[n2*2+1]);
                    mma_bf16(oacc[nt], pah[kk], vbl[n2*2], vbl[n2*2+1]);
                    mma_bf16(oacc[nt], pal[kk], vbh[n2*2], vbh[n2*2+1]);
                }
            }
        }
    }

    lrun0 += __shfl_xor_sync(0xffffffffu, lrun0, 1);
    lrun0 += __shfl_xor_sync(0xffffffffu, lrun0, 2);
    lrun1 += __shfl_xor_sync(0xffffffffu, lrun1, 1);
    lrun1 += __shfl_xor_sync(0xffffffffu, lrun1, 2);
    const float inv0 = 1.0f / lrun0, inv1 = 1.0f / lrun1;

    const int bb = bh >> 4, hh_ = bh & 15;
    #pragma unroll
    for (int nt = 0; nt < 8; nt++) {
        const int col = hh_*64 + nt*8 + (l & 3)*2;
        #pragma unroll
        for (int half = 0; half < 2; half++) {
            const float inv = half ? inv1 : inv0;
            float f0 = oacc[nt][half*2+0] * inv;
            float f1 = oacc[nt][half*2+1] * inv;
            __nv_bfloat16 h0,l0,h1,l1;
            bsplit(f0, h0, l0); bsplit(f1, h1, l1);
            const int gi = it*128 + w*16 + (l>>2) + half*8;
            const size_t o = ((size_t)bb*N_ + gi)*C_ + col;
            *(uint32_t*)&g_aoh[o] = pack_bf2(h0, h1);
            *(uint32_t*)&g_aol[o] = pack_bf2(l0, l1);
        }
    }
}

extern "C" void kernel_launch(void* const* d_in, const int* in_sizes, int n_in,
                              void* d_out, int out_size) {
    const float* x    = (const float*)d_in[0];
    const float* Wqkv = (const float*)d_in[1];
    const float* Wout = (const float*)d_in[2];
    const float* bout = (const float*)d_in[3];
    float* out = (float*)d_out;

    cudaFuncSetAttribute(gemm_qkv_mma, cudaFuncAttributeMaxDynamicSharedMemorySize, GEMM_SMEM);
    cudaFuncSetAttribute(gemm_out_mma, cudaFuncAttributeMaxDynamicSharedMemorySize, GEMM_SMEM);
    cudaFuncSetAttribute(attn_mma, cudaFuncAttributeMaxDynamicSharedMemorySize, ATTN_SMEM);

    split_x<<<4096, 256>>>(x);
    split_wT<<<dim3(96, 32), dim3(32, 8)>>>(Wqkv, 3072, 0);
    split_wT<<<dim3(32, 32), dim3(32, 8)>>>(Wout, 1024, 1);
    gemm_qkv_mma<<<dim3(24, 32), 256, GEMM_SMEM>>>();
    attn_mma<<<dim3(16, 32), 256, ATTN_SMEM>>>();
    gemm_out_mma<<<dim3(8, 32), 256, GEMM_SMEM>>>(bout, out);
}

// round 14
// speedup vs baseline: 1.0043x; 1.0043x over previous
#include <cuda_runtime.h>
#include <cuda_bf16.h>
#include <cstdint>
#include <math.h>

#define B_   2
#define H_   16
#define N_   2048
#define D_   64
#define C_   1024
#define BH_  (B_*H_)

// bf16 hi/lo scratch
__device__ __nv_bfloat16 g_xh[4096*1024], g_xl[4096*1024];     // X split, [row][k]
__device__ __nv_bfloat16 g_wqh[3072*1024], g_wql[3072*1024];   // Wqkv^T split, [n][k]
__device__ __nv_bfloat16 g_woh[1024*1024], g_wol[1024*1024];   // Wout^T split, [n][k]
__device__ __nv_bfloat16 g_aoh[4096*1024], g_aol[4096*1024];   // attn out split, [row][k]
// attention operands (written by gemm_qkv_mma epilogue)
__device__ __nv_bfloat16 g_qh2[BH_*N_*D_], g_ql2[BH_*N_*D_];   // [bh][tok][64], *log2e/32
__device__ __nv_bfloat16 g_kh2[BH_*N_*D_], g_kl2[BH_*N_*D_];   // [bh][tok][64]
__device__ __nv_bfloat16 g_vth[BH_*N_*D_], g_vtl[BH_*N_*D_];   // [bh][d][tok]  (transposed)

// ---- helpers ----
__device__ __forceinline__ uint32_t smem_u32(const void* p) {
    uint32_t a;
    asm("{ .reg .u64 t; cvta.to.shared.u64 t, %1; cvt.u32.u64 %0, t; }" : "=r"(a) : "l"(p));
    return a;
}
__device__ __forceinline__ void ldmx4(uint32_t* r, uint32_t addr) {
    asm volatile("ldmatrix.sync.aligned.m8n8.x4.shared.b16 {%0,%1,%2,%3}, [%4];"
                 : "=r"(r[0]), "=r"(r[1]), "=r"(r[2]), "=r"(r[3]) : "r"(addr));
}
__device__ __forceinline__ void mma_bf16(float* d, const uint32_t* a, uint32_t b0, uint32_t b1) {
    asm volatile("mma.sync.aligned.m16n8k16.row.col.f32.bf16.bf16.f32 "
                 "{%0,%1,%2,%3}, {%4,%5,%6,%7}, {%8,%9}, {%0,%1,%2,%3};"
                 : "+f"(d[0]), "+f"(d[1]), "+f"(d[2]), "+f"(d[3])
                 : "r"(a[0]), "r"(a[1]), "r"(a[2]), "r"(a[3]), "r"(b0), "r"(b1));
}
__device__ __forceinline__ void bsplit(float v, __nv_bfloat16& h, __nv_bfloat16& l) {
    h = __float2bfloat16_rn(v);
    l = __float2bfloat16_rn(v - __bfloat162float(h));
}
__device__ __forceinline__ uint32_t pack_bf2(__nv_bfloat16 lo, __nv_bfloat16 hi) {
    __nv_bfloat162 p; p.x = lo; p.y = hi;
    return *(uint32_t*)&p;
}
__device__ __forceinline__ void cp16(uint32_t saddr, const void* gaddr) {
    asm volatile("cp.async.cg.shared.global [%0], [%1], 16;" :: "r"(saddr), "l"(gaddr));
}
#define CP_COMMIT() asm volatile("cp.async.commit_group;" ::: "memory")
#define CP_WAIT(n)  asm volatile("cp.async.wait_group %0;" :: "n"(n) : "memory")

// ===========================================================================
// Splitters
// ===========================================================================
__global__ void __launch_bounds__(256) split_x(const float* __restrict__ X) {
    int i = blockIdx.x*256 + threadIdx.x;
    float4 v = ((const float4*)X)[i];
    __nv_bfloat16 h[4], l[4];
    bsplit(v.x, h[0], l[0]); bsplit(v.y, h[1], l[1]);
    bsplit(v.z, h[2], l[2]); bsplit(v.w, h[3], l[3]);
    *(uint2*)&g_xh[(size_t)i*4] = *(uint2*)h;
    *(uint2*)&g_xl[(size_t)i*4] = *(uint2*)l;
}

__global__ void __launch_bounds__(256) split_wT(const float* __restrict__ W, int Nn, int which) {
    __shared__ float sm[32][33];
    const int tx = threadIdx.x, ty = threadIdx.y;
    const int nx = blockIdx.x*32, kx = blockIdx.y*32;
    #pragma unroll
    for (int i = 0; i < 4; i++)
        sm[ty + i*8][tx] = W[(size_t)(kx + ty + i*8)*Nn + nx + tx];
    __syncthreads();
    __nv_bfloat16* Th = which ? g_woh : g_wqh;
    __nv_bfloat16* Tl = which ? g_wol : g_wql;
    #pragma unroll
    for (int i = 0; i < 4; i++) {
        float v = sm[tx][ty + i*8];
        __nv_bfloat16 h, l; bsplit(v, h, l);
        size_t o = (size_t)(nx + ty + i*8)*1024 + kx + tx;
        Th[o] = h; Tl[o] = l;
    }
}

// ===========================================================================
// bf16 3-pass mma GEMM, 3-stage cp.async pipeline (k16 stages — R12 config).
// CTA 128x128, 8 warps (2m x 4n), warp 64x32. Stage = 16KB.
// ===========================================================================
#define GSTAGE 16384
#define VSTRIDE 272                      // bytes per col row in V staging
#define QKV_SMEM (128*VSTRIDE*2)         // 69632 (>= 3*GSTAGE)
#define OUT_SMEM (3*GSTAGE)

struct MmaCtx {
    float acc[4][4][4];
    uint32_t sb;
    int offA, offB;
    int wm, wn, lane;
    const char *gAh, *gAl, *gBh, *gBl;
    uint32_t dA;
};

__device__ __forceinline__ void mma_init(MmaCtx& c, void* smem,
        const __nv_bfloat16* Ah, const __nv_bfloat16* Al,
        const __nv_bfloat16* Bh, const __nv_bfloat16* Bl,
        int bm, int bn) {
    const int t = threadIdx.x, l = t & 31, w = t >> 5;
    c.lane = l; c.wm = w & 1; c.wn = w >> 1;
    c.sb = smem_u32(smem);
    #pragma unroll
    for (int a = 0; a < 4; a++)
        #pragma unroll
        for (int b = 0; b < 4; b++)
            #pragma unroll
            for (int d = 0; d < 4; d++) c.acc[a][b][d] = 0.f;

    const int arow = t & 127, akc = t >> 7;
    c.gAh = (const char*)(Ah + (size_t)(bm*128 + arow)*1024) + akc*16;
    c.gAl = (const char*)(Al + (size_t)(bm*128 + arow)*1024) + akc*16;
    c.gBh = (const char*)(Bh + (size_t)(bn*128 + arow)*1024) + akc*16;
    c.gBl = (const char*)(Bl + (size_t)(bn*128 + arow)*1024) + akc*16;
    c.dA = (uint32_t)((akc*128 + arow)*16);

    const int rowA = c.wm*64 + ((l>>3)&1)*8 + (l&7), kcA = l>>4;
    c.offA = (kcA*128 + rowA)*16;
    const int nB = c.wn*32 + (l&7) + (l>>4)*8, kcB = (l>>3)&1;
    c.offB = (kcB*128 + nB)*16;
}

__device__ __forceinline__ void mma_issue(MmaCtx& c, int j, int slot) {
    const uint32_t S = c.sb + slot*GSTAGE + c.dA;
    const size_t go = (size_t)j * 32;
    cp16(S,          c.gAh + go);
    cp16(S + 4096,   c.gAl + go);
    cp16(S + 8192,   c.gBh + go);
    cp16(S + 12288,  c.gBl + go);
    CP_COMMIT();
}

__device__ __forceinline__ void mma_compute(MmaCtx& c, int slot) {
    const uint32_t S = c.sb + slot*GSTAGE;
    uint32_t Ah_[4][4], Al_[4][4];
    #pragma unroll
    for (int mt = 0; mt < 4; mt++) {
        ldmx4(Ah_[mt], S + c.offA + mt*256);
        ldmx4(Al_[mt], S + 4096 + c.offA + mt*256);
    }
    #pragma unroll
    for (int ntp = 0; ntp < 2; ntp++) {
        uint32_t bh[4], bl[4];
        ldmx4(bh, S + 8192 + c.offB + ntp*256);
        ldmx4(bl, S + 12288 + c.offB + ntp*256);
        #pragma unroll
        for (int n2 = 0; n2 < 2; n2++) {
            const int nt = ntp*2 + n2;
            #pragma unroll
            for (int mt = 0; mt < 4; mt++) {
                mma_bf16(c.acc[mt][nt], Ah_[mt], bh[n2*2], bh[n2*2+1]);
                mma_bf16(c.acc[mt][nt], Ah_[mt], bl[n2*2], bl[n2*2+1]);
                mma_bf16(c.acc[mt][nt], Al_[mt], bh[n2*2], bh[n2*2+1]);
            }
        }
    }
}

#define MMA_MAIN(c)                                        \
    mma_issue(c, 0, 0); mma_issue(c, 1, 1);                \
    for (int j = 0; j < 64; j++) {                         \
        CP_WAIT(1);                                        \
        __syncthreads();                                   \
        if (j + 2 < 64) mma_issue(c, j+2, (j+2)%3);        \
        mma_compute(c, j%3);                               \
    }

__global__ void __launch_bounds__(256, 2) gemm_qkv_mma() {
    extern __shared__ __align__(16) char smem[];
    MmaCtx c;
    const int bn = blockIdx.x, bm = blockIdx.y;
    mma_init(c, smem, g_xh, g_xl, g_wqh, g_wql, bm, bn);
    MMA_MAIN(c);

    const int sel = bn >> 3;
    const int t = threadIdx.x;
    if (sel == 2) {
        // ---- V: stage [colLocal][tok] in smem, then coalesced store ----
        __syncthreads();   // all warps done reading stage smem
        #pragma unroll
        for (int mt = 0; mt < 4; mt++) {
            #pragma unroll
            for (int nt = 0; nt < 4; nt++) {
                const int colL = c.wn*32 + nt*8 + (c.lane & 3)*2;
                #pragma unroll
                for (int half = 0; half < 2; half++) {
                    const int tok = c.wm*64 + mt*16 + (c.lane >> 2) + half*8;
                    __nv_bfloat16 h0,l0,h1,l1;
                    bsplit(c.acc[mt][nt][half*2+0], h0, l0);
                    bsplit(c.acc[mt][nt][half*2+1], h1, l1);
                    *(__nv_bfloat16*)(smem + (colL+0)*VSTRIDE + tok*2)       = h0;
                    *(__nv_bfloat16*)(smem + (colL+1)*VSTRIDE + tok*2)       = h1;
                    *(__nv_bfloat16*)(smem + 128*VSTRIDE + (colL+0)*VSTRIDE + tok*2) = l0;
                    *(__nv_bfloat16*)(smem + 128*VSTRIDE + (colL+1)*VSTRIDE + tok*2) = l1;
                }
            }
        }
        __syncthreads();
        // 256 threads: each copies one (colL, half) row of 128 tok = 256B
        const int colL = t & 127, hf = t >> 7;
        const int nn = (bn & 7)*128 + colL;
        const int h = nn >> 6, d = nn & 63;
        const int bb = (bm*128) >> 11, nr0 = (bm*128) & 2047;
        __nv_bfloat16* dst = hf ? g_vtl : g_vth;
        const char* src = smem + hf*(128*VSTRIDE) + colL*VSTRIDE;
        char* dg = (char*)(dst + ((size_t)((bb*H_ + h)*D_ + d))*N_ + nr0);
        #pragma unroll
        for (int u = 0; u < 16; u++)
            *(uint4*)(dg + u*16) = *(const uint4*)(src + u*16);
    } else {
        const float sc = (sel == 0) ? 0.03125f * 1.4426950408889634f : 1.0f;
        #pragma unroll
        for (int mt = 0; mt < 4; mt++) {
            const int row0 = bm*128 + c.wm*64 + mt*16 + (c.lane >> 2);
            #pragma unroll
            for (int nt = 0; nt < 4; nt++) {
                const int col = (bn & 7)*128 + c.wn*32 + nt*8 + (c.lane & 3)*2;
                const int h = col >> 6, d = col & 63;
                #pragma unroll
                for (int half = 0; half < 2; half++) {
                    const int r = row0 + half*8;
                    const int bb = r >> 11, nr = r & 2047;
                    const int bh_ = bb*H_ + h;
                    float f0 = c.acc[mt][nt][half*2+0]*sc;
                    float f1 = c.acc[mt][nt][half*2+1]*sc;
                    __nv_bfloat16 h0,l0,h1,l1;
                    bsplit(f0, h0, l0); bsplit(f1, h1, l1);
                    size_t o = ((size_t)bh_*N_ + nr)*D_ + d;
                    __nv_bfloat16* Dh = sel ? g_kh2 : g_qh2;
                    __nv_bfloat16* Dl = sel ? g_kl2 : g_ql2;
                    *(uint32_t*)&Dh[o] = pack_bf2(h0, h1);
                    *(uint32_t*)&Dl[o] = pack_bf2(l0, l1);
                }
            }
        }
    }
}

__global__ void __launch_bounds__(256, 2) gemm_out_mma(const float* __restrict__ bias,
                                                       float* __restrict__ out) {
    extern __shared__ __align__(16) char smem[];
    MmaCtx c;
    const int bn = blockIdx.x, bm = blockIdx.y;
    mma_init(c, smem, g_aoh, g_aol, g_woh, g_wol, bm, bn);
    MMA_MAIN(c);

    #pragma unroll
    for (int mt = 0; mt < 4; mt++) {
        const int row0 = bm*128 + c.wm*64 + mt*16 + (c.lane >> 2);
        #pragma unroll
        for (int nt = 0; nt < 4; nt++) {
            const int col = bn*128 + c.wn*32 + nt*8 + (c.lane & 3)*2;
            const float2 bv = *(const float2*)&bias[col];
            #pragma unroll
            for (int half = 0; half < 2; half++) {
                const size_t r = (size_t)(row0 + half*8);
                float2 o = make_float2(c.acc[mt][nt][half*2+0] + bv.x,
                                       c.acc[mt][nt][half*2+1] + bv.y);
                *(float2*)&out[r*C_ + col] = o;
            }
        }
    }
}

// ===========================================================================
// Attention on mma.sync, cp.async double-buffered K/V (unchanged from R12).
// ===========================================================================
#define ATTN_SMEM 98304

__global__ void __launch_bounds__(256) attn_mma() {
    extern __shared__ __align__(16) char smem[];
    char* sQ = smem;
    const uint32_t sbQ = smem_u32(sQ);
    const uint32_t sbKV = sbQ + 32768;

    const int t = threadIdx.x, l = t & 31, w = t >> 5;
    const int it = blockIdx.x, bh = blockIdx.y;
    const size_t base = (size_t)bh * (N_*D_);

    {
        const int row = t & 127;
        const int kcb0 = (t >> 7) * 4;
        const uint4* gh = (const uint4*)(g_qh2 + base + (size_t)(it*128 + row)*D_);
        const uint4* gl = (const uint4*)(g_ql2 + base + (size_t)(it*128 + row)*D_);
        #pragma unroll
        for (int u = 0; u < 4; u++) {
            const int kcb = kcb0 + u;
            *(uint4*)(sQ + (kcb*128 + row)*16)         = gh[kcb];
            *(uint4*)(sQ + 16384 + (kcb*128 + row)*16) = gl[kcb];
        }
    }

    const int rowQ = w*16 + ((l>>3)&1)*8 + (l&7);
    const int offQ = rowQ*16 + (l>>4)*2048;
    const int offB = (((l>>3)&1)*64 + (l&7) + (l>>4)*8)*16;

    const int jrow = t & 63;
    const int kcb2 = (t >> 6) * 2;
    const char* gKh = (const char*)(g_kh2 + base + (size_t)jrow*D_) + kcb2*16;
    const char* gKl = (const char*)(g_kl2 + base + (size_t)jrow*D_) + kcb2*16;
    const char* gVh = (const char*)(g_vth + base + (size_t)jrow*N_) + kcb2*16;
    const char* gVl = (const char*)(g_vtl + base + (size_t)jrow*N_) + kcb2*16;
    const uint32_t dK = (uint32_t)((kcb2*64 + jrow)*16);

    auto kv_issue = [&](int jt, int slot) {
        const uint32_t S = sbKV + slot*32768 + dK;
        const size_t koff = (size_t)jt * 64 * D_ * 2;
        const size_t voff = (size_t)jt * 64 * 2;
        #pragma unroll
        for (int u = 0; u < 2; u++) {
            cp16(S + u*1024,          gKh + koff + u*16);
            cp16(S + 8192 + u*1024,   gKl + koff + u*16);
            cp16(S + 16384 + u*1024,  gVh + voff + u*16);
            cp16(S + 24576 + u*1024,  gVl + voff + u*16);
        }
        CP_COMMIT();
    };

    float oacc[8][4];
    #pragma unroll
    for (int nt = 0; nt < 8; nt++)
        #pragma unroll
        for (int d = 0; d < 4; d++) oacc[nt][d] = 0.f;
    float lrun0 = 0.f, lrun1 = 0.f;

    const int row_glob0 = it*128 + w*16 + (l>>2);

    kv_issue(0, 0);

    for (int jt = 0; jt < 32; jt++) {
        CP_WAIT(0);
        __syncthreads();
        if (jt + 1 < 32) kv_issue(jt+1, (jt+1)&1);

        const uint32_t sbK = sbKV + (jt&1)*32768;
        const uint32_t sbV = sbK + 16384;

        float sacc[8][4];
        #pragma unroll
        for (int nt = 0; nt < 8; nt++)
            #pragma unroll
            for (int d = 0; d < 4; d++) sacc[nt][d] = 0.f;

        #pragma unroll
        for (int kc = 0; kc < 4; kc++) {
            uint32_t qh[4], ql[4];
            ldmx4(qh, sbQ + offQ + kc*4096);
            ldmx4(ql, sbQ + 16384 + offQ + kc*4096);
            #pragma unroll
            for (int np = 0; np < 4; np++) {
                uint32_t kbh[4], kbl[4];
                ldmx4(kbh, sbK + kc*2048 + offB + np*256);
                ldmx4(kbl, sbK + 8192 + kc*2048 + offB + np*256);
                #pragma unroll
                for (int n2 = 0; n2 < 2; n2++) {
                    const int nt = np*2 + n2;
                    mma_bf16(sacc[nt], qh, kbh[n2*2], kbh[n2*2+1]);
                    mma_bf16(sacc[nt], qh, kbl[n2*2], kbl[n2*2+1]);
                    mma_bf16(sacc[nt], ql, kbh[n2*2], kbh[n2*2+1]);
                }
            }
        }

        uint32_t pah[4][4], pal[4][4];
        #pragma unroll
        for (int nt = 0; nt < 8; nt++) {
            const int colb = jt*64 + nt*8 + (l & 3)*2;
            const int del0 = row_glob0 - colb;
            const int dels[4] = {del0, del0 - 1, del0 + 8, del0 + 7};
            float p[4];
            #pragma unroll
            for (int e = 0; e < 4; e++) {
                const int de = dels[e];
                const bool msk = (de >= 0) && ((de & 31) == 0);
                p[e] = msk ? 0.f : exp2f(sacc[nt][e]);
            }
            lrun0 += p[0] + p[1];
            lrun1 += p[2] + p[3];
            __nv_bfloat16 h0,l0,h1,l1,h2,l2,h3,l3;
            bsplit(p[0], h0, l0); bsplit(p[1], h1, l1);
            bsplit(p[2], h2, l2); bsplit(p[3], h3, l3);
            const int kk = nt >> 1, sl = (nt & 1)*2;
            pah[kk][sl+0] = pack_bf2(h0, h1);
            pah[kk][sl+1] = pack_bf2(h2, h3);
            pal[kk][sl+0] = pack_bf2(l0, l1);
            pal[kk][sl+1] = pack_bf2(l2, l3);
        }

        #pragma unroll
        for (int kk = 0; kk < 4; kk++) {
            #pragma unroll
            for (int np = 0; np < 4; np++) {
                uint32_t vbh[4], vbl[4];
                ldmx4(vbh, sbV + kk*2048 + offB + np*256);
                ldmx4(vbl, sbV + 8192 + kk*2048 + offB + np*256);
                #pragma unroll
                for (int n2 = 0; n2 < 2; n2++) {
                    const int nt = np*2 + n2;
                    mma_bf16(oacc[nt], pah[kk], vbh[n2*2], vbh[n2*2+1]);
                    mma_bf16(oacc[nt], pah[kk], vbl[n2*2], vbl[n2*2+1]);
                    mma_bf16(oacc[nt], pal[kk], vbh[n2*2], vbh[n2*2+1]);
                }
            }
        }
    }

    lrun0 += __shfl_xor_sync(0xffffffffu, lrun0, 1);
    lrun0 += __shfl_xor_sync(0xffffffffu, lrun0, 2);
    lrun1 += __shfl_xor_sync(0xffffffffu, lrun1, 1);
    lrun1 += __shfl_xor_sync(0xffffffffu, lrun1, 2);
    const float inv0 = 1.0f / lrun0, inv1 = 1.0f / lrun1;

    const int bb = bh >> 4, hh_ = bh & 15;
    #pragma unroll
    for (int nt = 0; nt < 8; nt++) {
        const int col = hh_*64 + nt*8 + (l & 3)*2;
        #pragma unroll
        for (int half = 0; half < 2; half++) {
            const float inv = half ? inv1 : inv0;
            float f0 = oacc[nt][half*2+0] * inv;
            float f1 = oacc[nt][half*2+1] * inv;
            __nv_bfloat16 h0,l0,h1,l1;
            bsplit(f0, h0, l0); bsplit(f1, h1, l1);
            const int gi = it*128 + w*16 + (l>>2) + half*8;
            const size_t o = ((size_t)bb*N_ + gi)*C_ + col;
            *(uint32_t*)&g_aoh[o] = pack_bf2(h0, h1);
            *(uint32_t*)&g_aol[o] = pack_bf2(l0, l1);
        }
    }
}

extern "C" void kernel_launch(void* const* d_in, const int* in_sizes, int n_in,
                              void* d_out, int out_size) {
    const float* x    = (const float*)d_in[0];
    const float* Wqkv = (const float*)d_in[1];
    const float* Wout = (const float*)d_in[2];
    const float* bout = (const float*)d_in[3];
    float* out = (float*)d_out;

    cudaFuncSetAttribute(gemm_qkv_mma, cudaFuncAttributeMaxDynamicSharedMemorySize, QKV_SMEM);
    cudaFuncSetAttribute(gemm_out_mma, cudaFuncAttributeMaxDynamicSharedMemorySize, OUT_SMEM);
    cudaFuncSetAttribute(attn_mma, cudaFuncAttributeMaxDynamicSharedMemorySize, ATTN_SMEM);

    split_x<<<4096, 256>>>(x);
    split_wT<<<dim3(96, 32), dim3(32, 8)>>>(Wqkv, 3072, 0);
    split_wT<<<dim3(32, 32), dim3(32, 8)>>>(Wout, 1024, 1);
    gemm_qkv_mma<<<dim3(24, 32), 256, QKV_SMEM>>>();
    attn_mma<<<dim3(16, 32), 256, ATTN_SMEM>>>();
    gemm_out_mma<<<dim3(8, 32), 256, OUT_SMEM>>>(bout, out);
}

// round 15
// speedup vs baseline: 1.1124x; 1.1077x over previous
#include <cuda_runtime.h>
#include <cuda_bf16.h>
#include <cstdint>
#include <math.h>

#define B_   2
#define H_   16
#define N_   2048
#define D_   64
#define C_   1024
#define BH_  (B_*H_)

// bf16 hi/lo scratch
__device__ __nv_bfloat16 g_xh[4096*1024], g_xl[4096*1024];     // X split, [row][k]
__device__ __nv_bfloat16 g_wqh[3072*1024], g_wql[3072*1024];   // Wqkv^T split, [n][k]
__device__ __nv_bfloat16 g_woh[1024*1024], g_wol[1024*1024];   // Wout^T split, [n][k]
__device__ __nv_bfloat16 g_aoh[4096*1024], g_aol[4096*1024];   // attn out split, [row][k]
// attention operands (written by gemm_qkv_mma epilogue)
__device__ __nv_bfloat16 g_qh2[BH_*N_*D_], g_ql2[BH_*N_*D_];   // [bh][tok][64], *log2e/32
__device__ __nv_bfloat16 g_kh2[BH_*N_*D_], g_kl2[BH_*N_*D_];   // [bh][tok][64]
__device__ __nv_bfloat16 g_vth[BH_*N_*D_], g_vtl[BH_*N_*D_];   // [bh][d][tok]  (transposed)

// ---- helpers ----
__device__ __forceinline__ uint32_t smem_u32(const void* p) {
    uint32_t a;
    asm("{ .reg .u64 t; cvta.to.shared.u64 t, %1; cvt.u32.u64 %0, t; }" : "=r"(a) : "l"(p));
    return a;
}
__device__ __forceinline__ void ldmx4(uint32_t* r, uint32_t addr) {
    asm volatile("ldmatrix.sync.aligned.m8n8.x4.shared.b16 {%0,%1,%2,%3}, [%4];"
                 : "=r"(r[0]), "=r"(r[1]), "=r"(r[2]), "=r"(r[3]) : "r"(addr));
}
__device__ __forceinline__ void mma_bf16(float* d, const uint32_t* a, uint32_t b0, uint32_t b1) {
    asm volatile("mma.sync.aligned.m16n8k16.row.col.f32.bf16.bf16.f32 "
                 "{%0,%1,%2,%3}, {%4,%5,%6,%7}, {%8,%9}, {%0,%1,%2,%3};"
                 : "+f"(d[0]), "+f"(d[1]), "+f"(d[2]), "+f"(d[3])
                 : "r"(a[0]), "r"(a[1]), "r"(a[2]), "r"(a[3]), "r"(b0), "r"(b1));
}
__device__ __forceinline__ void bsplit(float v, __nv_bfloat16& h, __nv_bfloat16& l) {
    h = __float2bfloat16_rn(v);
    l = __float2bfloat16_rn(v - __bfloat162float(h));
}
__device__ __forceinline__ uint32_t pack_bf2(__nv_bfloat16 lo, __nv_bfloat16 hi) {
    __nv_bfloat162 p; p.x = lo; p.y = hi;
    return *(uint32_t*)&p;
}
__device__ __forceinline__ void cp16(uint32_t saddr, const void* gaddr) {
    asm volatile("cp.async.cg.shared.global [%0], [%1], 16;" :: "r"(saddr), "l"(gaddr));
}
#define CP_COMMIT() asm volatile("cp.async.commit_group;" ::: "memory")
#define CP_WAIT(n)  asm volatile("cp.async.wait_group %0;" :: "n"(n) : "memory")

// ===========================================================================
// Splitters
// ===========================================================================
__global__ void __launch_bounds__(256) split_x(const float* __restrict__ X) {
    int i = blockIdx.x*256 + threadIdx.x;
    float4 v = ((const float4*)X)[i];
    __nv_bfloat16 h[4], l[4];
    bsplit(v.x, h[0], l[0]); bsplit(v.y, h[1], l[1]);
    bsplit(v.z, h[2], l[2]); bsplit(v.w, h[3], l[3]);
    *(uint2*)&g_xh[(size_t)i*4] = *(uint2*)h;
    *(uint2*)&g_xl[(size_t)i*4] = *(uint2*)l;
}

__global__ void __launch_bounds__(256) split_wT(const float* __restrict__ W, int Nn, int which) {
    __shared__ float sm[32][33];
    const int tx = threadIdx.x, ty = threadIdx.y;
    const int nx = blockIdx.x*32, kx = blockIdx.y*32;
    #pragma unroll
    for (int i = 0; i < 4; i++)
        sm[ty + i*8][tx] = W[(size_t)(kx + ty + i*8)*Nn + nx + tx];
    __syncthreads();
    __nv_bfloat16* Th = which ? g_woh : g_wqh;
    __nv_bfloat16* Tl = which ? g_wol : g_wql;
    #pragma unroll
    for (int i = 0; i < 4; i++) {
        float v = sm[tx][ty + i*8];
        __nv_bfloat16 h, l; bsplit(v, h, l);
        size_t o = (size_t)(nx + ty + i*8)*1024 + kx + tx;
        Th[o] = h; Tl[o] = l;
    }
}

// ===========================================================================
// bf16 3-pass mma GEMM: CTA 128x128, 4 warps (2m x 2n), warp tile 64x64.
// k16 stages, 4-stage cp.async pipeline (64KB). 96 mma / 16 ldmx4 per chunk.
// Stage layout: Ah@0 Al@4096 Bh@8192 Bl@12288, each [kc(2)][128][16B].
// ===========================================================================
#define GSTAGE 16384
#define GEMM_SMEM (4*GSTAGE)

struct MmaCtx {
    float acc[4][8][4];                  // [mt][nt][frag]
    uint32_t sb;
    int offA, offB;
    int wm, wn, lane;
    const char *gAh, *gAl, *gBh, *gBl;   // per-thread row base (row t)
};

__device__ __forceinline__ void mma_init(MmaCtx& c, void* smem,
        const __nv_bfloat16* Ah, const __nv_bfloat16* Al,
        const __nv_bfloat16* Bh, const __nv_bfloat16* Bl,
        int bm, int bn) {
    const int t = threadIdx.x, l = t & 31, w = t >> 5;
    c.lane = l; c.wm = w & 1; c.wn = w >> 1;
    c.sb = smem_u32(smem);
    #pragma unroll
    for (int a = 0; a < 4; a++)
        #pragma unroll
        for (int b = 0; b < 8; b++)
            #pragma unroll
            for (int d = 0; d < 4; d++) c.acc[a][b][d] = 0.f;

    c.gAh = (const char*)(Ah + (size_t)(bm*128 + t)*1024);
    c.gAl = (const char*)(Al + (size_t)(bm*128 + t)*1024);
    c.gBh = (const char*)(Bh + (size_t)(bn*128 + t)*1024);
    c.gBl = (const char*)(Bl + (size_t)(bn*128 + t)*1024);

    const int rowA = c.wm*64 + ((l>>3)&1)*8 + (l&7), kcA = l>>4;
    c.offA = (kcA*128 + rowA)*16;
    const int nB = c.wn*64 + (l&7) + (l>>4)*8, kcB = (l>>3)&1;
    c.offB = (kcB*128 + nB)*16;
}

__device__ __forceinline__ void mma_issue(MmaCtx& c, int j, int slot) {
    const int t = threadIdx.x;
    const uint32_t S = c.sb + slot*GSTAGE;
    const uint32_t d0 = (uint32_t)(t*16), d1 = (uint32_t)((128 + t)*16);
    const size_t go = (size_t)j * 32;
    cp16(S + d0,          c.gAh + go);
    cp16(S + d1,          c.gAh + go + 16);
    cp16(S + 4096 + d0,   c.gAl + go);
    cp16(S + 4096 + d1,   c.gAl + go + 16);
    cp16(S + 8192 + d0,   c.gBh + go);
    cp16(S + 8192 + d1,   c.gBh + go + 16);
    cp16(S + 12288 + d0,  c.gBl + go);
    cp16(S + 12288 + d1,  c.gBl + go + 16);
    CP_COMMIT();
}

__device__ __forceinline__ void mma_compute(MmaCtx& c, int slot) {
    const uint32_t S = c.sb + slot*GSTAGE;
    uint32_t Ah_[4][4], Al_[4][4];
    #pragma unroll
    for (int mt = 0; mt < 4; mt++) {
        ldmx4(Ah_[mt], S + c.offA + mt*256);
        ldmx4(Al_[mt], S + 4096 + c.offA + mt*256);
    }
    #pragma unroll
    for (int ntp = 0; ntp < 4; ntp++) {
        uint32_t bh[4], bl[4];
        ldmx4(bh, S + 8192 + c.offB + ntp*256);
        ldmx4(bl, S + 12288 + c.offB + ntp*256);
        #pragma unroll
        for (int n2 = 0; n2 < 2; n2++) {
            const int nt = ntp*2 + n2;
            #pragma unroll
            for (int mt = 0; mt < 4; mt++) {
                mma_bf16(c.acc[mt][nt], Ah_[mt], bh[n2*2], bh[n2*2+1]);
                mma_bf16(c.acc[mt][nt], Ah_[mt], bl[n2*2], bl[n2*2+1]);
                mma_bf16(c.acc[mt][nt], Al_[mt], bh[n2*2], bh[n2*2+1]);
            }
        }
    }
}

#define MMA_MAIN(c)                                        \
    mma_issue(c, 0, 0); mma_issue(c, 1, 1); mma_issue(c, 2, 2); \
    for (int j = 0; j < 64; j++) {                         \
        CP_WAIT(2);                                        \
        __syncthreads();                                   \
        if (j + 3 < 64) mma_issue(c, j+3, (j+3)&3);        \
        mma_compute(c, j&3);                               \
    }

__global__ void __launch_bounds__(128, 2) gemm_qkv_mma() {
    extern __shared__ __align__(16) char smem[];
    MmaCtx c;
    const int bn = blockIdx.x, bm = blockIdx.y;
    mma_init(c, smem, g_xh, g_xl, g_wqh, g_wql, bm, bn);
    MMA_MAIN(c);

    const int sel = bn >> 3;
    const float sc = (sel == 0) ? 0.03125f * 1.4426950408889634f : 1.0f;
    #pragma unroll
    for (int mt = 0; mt < 4; mt++) {
        const int row0 = bm*128 + c.wm*64 + mt*16 + (c.lane >> 2);
        #pragma unroll
        for (int nt = 0; nt < 8; nt++) {
            const int col = (bn & 7)*128 + c.wn*64 + nt*8 + (c.lane & 3)*2;
            const int h = col >> 6, d = col & 63;
            #pragma unroll
            for (int half = 0; half < 2; half++) {
                const int r = row0 + half*8;
                const int bb = r >> 11, nr = r & 2047;
                const int bh_ = bb*H_ + h;
                float f0 = c.acc[mt][nt][half*2+0]*sc;
                float f1 = c.acc[mt][nt][half*2+1]*sc;
                __nv_bfloat16 h0,l0,h1,l1;
                bsplit(f0, h0, l0); bsplit(f1, h1, l1);
                if (sel == 2) {
                    size_t o = ((size_t)bh_*D_ + d)*N_ + nr;
                    g_vth[o] = h0; g_vtl[o] = l0;
                    g_vth[o + N_] = h1; g_vtl[o + N_] = l1;
                } else {
                    size_t o = ((size_t)bh_*N_ + nr)*D_ + d;
                    __nv_bfloat16* Dh = sel ? g_kh2 : g_qh2;
                    __nv_bfloat16* Dl = sel ? g_kl2 : g_ql2;
                    *(uint32_t*)&Dh[o] = pack_bf2(h0, h1);
                    *(uint32_t*)&Dl[o] = pack_bf2(l0, l1);
                }
            }
        }
    }
}

__global__ void __launch_bounds__(128, 2) gemm_out_mma(const float* __restrict__ bias,
                                                       float* __restrict__ out) {
    extern __shared__ __align__(16) char smem[];
    MmaCtx c;
    const int bn = blockIdx.x, bm = blockIdx.y;
    mma_init(c, smem, g_aoh, g_aol, g_woh, g_wol, bm, bn);
    MMA_MAIN(c);

    #pragma unroll
    for (int mt = 0; mt < 4; mt++) {
        const int row0 = bm*128 + c.wm*64 + mt*16 + (c.lane >> 2);
        #pragma unroll
        for (int nt = 0; nt < 8; nt++) {
            const int col = bn*128 + c.wn*64 + nt*8 + (c.lane & 3)*2;
            const float2 bv = *(const float2*)&bias[col];
            #pragma unroll
            for (int half = 0; half < 2; half++) {
                const size_t r = (size_t)(row0 + half*8);
                float2 o = make_float2(c.acc[mt][nt][half*2+0] + bv.x,
                                       c.acc[mt][nt][half*2+1] + bv.y);
                *(float2*)&out[r*C_ + col] = o;
            }
        }
    }
}

// ===========================================================================
// Attention on mma.sync, cp.async double-buffered K/V (unchanged from R12).
// smem: sQ 32KB | stage0 KV 32KB | stage1 KV 32KB  = 96KB dynamic.
// ===========================================================================
#define ATTN_SMEM 98304

__global__ void __launch_bounds__(256) attn_mma() {
    extern __shared__ __align__(16) char smem[];
    char* sQ = smem;
    const uint32_t sbQ = smem_u32(sQ);
    const uint32_t sbKV = sbQ + 32768;

    const int t = threadIdx.x, l = t & 31, w = t >> 5;
    const int it = blockIdx.x, bh = blockIdx.y;
    const size_t base = (size_t)bh * (N_*D_);

    {
        const int row = t & 127;
        const int kcb0 = (t >> 7) * 4;
        const uint4* gh = (const uint4*)(g_qh2 + base + (size_t)(it*128 + row)*D_);
        const uint4* gl = (const uint4*)(g_ql2 + base + (size_t)(it*128 + row)*D_);
        #pragma unroll
        for (int u = 0; u < 4; u++) {
            const int kcb = kcb0 + u;
            *(uint4*)(sQ + (kcb*128 + row)*16)         = gh[kcb];
            *(uint4*)(sQ + 16384 + (kcb*128 + row)*16) = gl[kcb];
        }
    }

    const int rowQ = w*16 + ((l>>3)&1)*8 + (l&7);
    const int offQ = rowQ*16 + (l>>4)*2048;
    const int offB = (((l>>3)&1)*64 + (l&7) + (l>>4)*8)*16;

    const int jrow = t & 63;
    const int kcb2 = (t >> 6) * 2;
    const char* gKh = (const char*)(g_kh2 + base + (size_t)jrow*D_) + kcb2*16;
    const char* gKl = (const char*)(g_kl2 + base + (size_t)jrow*D_) + kcb2*16;
    const char* gVh = (const char*)(g_vth + base + (size_t)jrow*N_) + kcb2*16;
    const char* gVl = (const char*)(g_vtl + base + (size_t)jrow*N_) + kcb2*16;
    const uint32_t dK = (uint32_t)((kcb2*64 + jrow)*16);

    auto kv_issue = [&](int jt, int slot) {
        const uint32_t S = sbKV + slot*32768 + dK;
        const size_t koff = (size_t)jt * 64 * D_ * 2;
        const size_t voff = (size_t)jt * 64 * 2;
        #pragma unroll
        for (int u = 0; u < 2; u++) {
            cp16(S + u*1024,          gKh + koff + u*16);
            cp16(S + 8192 + u*1024,   gKl + koff + u*16);
            cp16(S + 16384 + u*1024,  gVh + voff + u*16);
            cp16(S + 24576 + u*1024,  gVl + voff + u*16);
        }
        CP_COMMIT();
    };

    float oacc[8][4];
    #pragma unroll
    for (int nt = 0; nt < 8; nt++)
        #pragma unroll
        for (int d = 0; d < 4; d++) oacc[nt][d] = 0.f;
    float lrun0 = 0.f, lrun1 = 0.f;

    const int row_glob0 = it*128 + w*16 + (l>>2);

    kv_issue(0, 0);

    for (int jt = 0; jt < 32; jt++) {
        CP_WAIT(0);
        __syncthreads();
        if (jt + 1 < 32) kv_issue(jt+1, (jt+1)&1);

        const uint32_t sbK = sbKV + (jt&1)*32768;
        const uint32_t sbV = sbK + 16384;

        float sacc[8][4];
        #pragma unroll
        for (int nt = 0; nt < 8; nt++)
            #pragma unroll
            for (int d = 0; d < 4; d++) sacc[nt][d] = 0.f;

        #pragma unroll
        for (int kc = 0; kc < 4; kc++) {
            uint32_t qh[4], ql[4];
            ldmx4(qh, sbQ + offQ + kc*4096);
            ldmx4(ql, sbQ + 16384 + offQ + kc*4096);
            #pragma unroll
            for (int np = 0; np < 4; np++) {
                uint32_t kbh[4], kbl[4];
                ldmx4(kbh, sbK + kc*2048 + offB + np*256);
                ldmx4(kbl, sbK + 8192 + kc*2048 + offB + np*256);
                #pragma unroll
                for (int n2 = 0; n2 < 2; n2++) {
                    const int nt = np*2 + n2;
                    mma_bf16(sacc[nt], qh, kbh[n2*2], kbh[n2*2+1]);
                    mma_bf16(sacc[nt], qh, kbl[n2*2], kbl[n2*2+1]);
                    mma_bf16(sacc[nt], ql, kbh[n2*2], kbh[n2*2+1]);
                }
            }
        }

        uint32_t pah[4][4], pal[4][4];
        #pragma unroll
        for (int nt = 0; nt < 8; nt++) {
            const int colb = jt*64 + nt*8 + (l & 3)*2;
            const int del0 = row_glob0 - colb;
            const int dels[4] = {del0, del0 - 1, del0 + 8, del0 + 7};
            float p[4];
            #pragma unroll
            for (int e = 0; e < 4; e++) {
                const int de = dels[e];
                const bool msk = (de >= 0) && ((de & 31) == 0);
                p[e] = msk ? 0.f : exp2f(sacc[nt][e]);
            }
            lrun0 += p[0] + p[1];
            lrun1 += p[2] + p[3];
            __nv_bfloat16 h0,l0,h1,l1,h2,l2,h3,l3;
            bsplit(p[0], h0, l0); bsplit(p[1], h1, l1);
            bsplit(p[2], h2, l2); bsplit(p[3], h3, l3);
            const int kk = nt >> 1, sl = (nt & 1)*2;
            pah[kk][sl+0] = pack_bf2(h0, h1);
            pah[kk][sl+1] = pack_bf2(h2, h3);
            pal[kk][sl+0] = pack_bf2(l0, l1);
            pal[kk][sl+1] = pack_bf2(l2, l3);
        }

        #pragma unroll
        for (int kk = 0; kk < 4; kk++) {
            #pragma unroll
            for (int np = 0; np < 4; np++) {
                uint32_t vbh[4], vbl[4];
                ldmx4(vbh, sbV + kk*2048 + offB + np*256);
                ldmx4(vbl, sbV + 8192 + kk*2048 + offB + np*256);
                #pragma unroll
                for (int n2 = 0; n2 < 2; n2++) {
                    const int nt = np*2 + n2;
                    mma_bf16(oacc[nt], pah[kk], vbh[n2*2], vbh[n2*2+1]);
                    mma_bf16(oacc[nt], pah[kk], vbl[n2*2], vbl[n2*2+1]);
                    mma_bf16(oacc[nt], pal[kk], vbh[n2*2], vbh[n2*2+1]);
                }
            }
        }
    }

    lrun0 += __shfl_xor_sync(0xffffffffu, lrun0, 1);
    lrun0 += __shfl_xor_sync(0xffffffffu, lrun0, 2);
    lrun1 += __shfl_xor_sync(0xffffffffu, lrun1, 1);
    lrun1 += __shfl_xor_sync(0xffffffffu, lrun1, 2);
    const float inv0 = 1.0f / lrun0, inv1 = 1.0f / lrun1;

    const int bb = bh >> 4, hh_ = bh & 15;
    #pragma unroll
    for (int nt = 0; nt < 8; nt++) {
        const int col = hh_*64 + nt*8 + (l & 3)*2;
        #pragma unroll
        for (int half = 0; half < 2; half++) {
            const float inv = half ? inv1 : inv0;
            float f0 = oacc[nt][half*2+0] * inv;
            float f1 = oacc[nt][half*2+1] * inv;
            __nv_bfloat16 h0,l0,h1,l1;
            bsplit(f0, h0, l0); bsplit(f1, h1, l1);
            const int gi = it*128 + w*16 + (l>>2) + half*8;
            const size_t o = ((size_t)bb*N_ + gi)*C_ + col;
            *(uint32_t*)&g_aoh[o] = pack_bf2(h0, h1);
            *(uint32_t*)&g_aol[o] = pack_bf2(l0, l1);
        }
    }
}

extern "C" void kernel_launch(void* const* d_in, const int* in_sizes, int n_in,
                              void* d_out, int out_size) {
    const float* x    = (const float*)d_in[0];
    const float* Wqkv = (const float*)d_in[1];
    const float* Wout = (const float*)d_in[2];
    const float* bout = (const float*)d_in[3];
    float* out = (float*)d_out;

    cudaFuncSetAttribute(gemm_qkv_mma, cudaFuncAttributeMaxDynamicSharedMemorySize, GEMM_SMEM);
    cudaFuncSetAttribute(gemm_out_mma, cudaFuncAttributeMaxDynamicSharedMemorySize, GEMM_SMEM);
    cudaFuncSetAttribute(attn_mma, cudaFuncAttributeMaxDynamicSharedMemorySize, ATTN_SMEM);

    split_x<<<4096, 256>>>(x);
    split_wT<<<dim3(96, 32), dim3(32, 8)>>>(Wqkv, 3072, 0);
    split_wT<<<dim3(32, 32), dim3(32, 8)>>>(Wout, 1024, 1);
    gemm_qkv_mma<<<dim3(24, 32), 128, GEMM_SMEM>>>();
    attn_mma<<<dim3(16, 32), 256, ATTN_SMEM>>>();
    gemm_out_mma<<<dim3(8, 32), 128, GEMM_SMEM>>>(bout, out);
}

// round 16
// speedup vs baseline: 1.3764x; 1.2373x over previous
#include <cuda_runtime.h>
#include <cuda_bf16.h>
#include <cuda_fp16.h>
#include <cstdint>
#include <math.h>

#define B_   2
#define H_   16
#define N_   2048
#define D_   64
#define C_   1024
#define BH_  (B_*H_)

// scratch
__device__ __nv_bfloat16 g_xh[4096*1024], g_xl[4096*1024];     // X split (bf16 hi/lo)
__device__ __nv_bfloat16 g_wqh[3072*1024], g_wql[3072*1024];   // Wqkv^T split (bf16 hi/lo)
__device__ __half        g_wo16[1024*1024];                    // Wout^T (fp16, rounded)
__device__ __half        g_ao16h[4096*1024], g_ao16l[4096*1024]; // attn out (fp16 hi/lo)
__device__ __nv_bfloat16 g_qh2[BH_*N_*D_];                     // Q (bf16 single), *log2e/32
__device__ __nv_bfloat16 g_kh2[BH_*N_*D_], g_kl2[BH_*N_*D_];   // K (bf16 hi/lo)
__device__ __half        g_v16[BH_*N_*D_];                     // V^T [bh][d][tok] (fp16)

// ---- helpers ----
__device__ __forceinline__ uint32_t smem_u32(const void* p) {
    uint32_t a;
    asm("{ .reg .u64 t; cvta.to.shared.u64 t, %1; cvt.u32.u64 %0, t; }" : "=r"(a) : "l"(p));
    return a;
}
__device__ __forceinline__ void ldmx4(uint32_t* r, uint32_t addr) {
    asm volatile("ldmatrix.sync.aligned.m8n8.x4.shared.b16 {%0,%1,%2,%3}, [%4];"
                 : "=r"(r[0]), "=r"(r[1]), "=r"(r[2]), "=r"(r[3]) : "r"(addr));
}
__device__ __forceinline__ void mma_bf16(float* d, const uint32_t* a, uint32_t b0, uint32_t b1) {
    asm volatile("mma.sync.aligned.m16n8k16.row.col.f32.bf16.bf16.f32 "
                 "{%0,%1,%2,%3}, {%4,%5,%6,%7}, {%8,%9}, {%0,%1,%2,%3};"
                 : "+f"(d[0]), "+f"(d[1]), "+f"(d[2]), "+f"(d[3])
                 : "r"(a[0]), "r"(a[1]), "r"(a[2]), "r"(a[3]), "r"(b0), "r"(b1));
}
__device__ __forceinline__ void mma_f16(float* d, const uint32_t* a, uint32_t b0, uint32_t b1) {
    asm volatile("mma.sync.aligned.m16n8k16.row.col.f32.f16.f16.f32 "
                 "{%0,%1,%2,%3}, {%4,%5,%6,%7}, {%8,%9}, {%0,%1,%2,%3};"
                 : "+f"(d[0]), "+f"(d[1]), "+f"(d[2]), "+f"(d[3])
                 : "r"(a[0]), "r"(a[1]), "r"(a[2]), "r"(a[3]), "r"(b0), "r"(b1));
}
__device__ __forceinline__ void bsplit(float v, __nv_bfloat16& h, __nv_bfloat16& l) {
    h = __float2bfloat16_rn(v);
    l = __float2bfloat16_rn(v - __bfloat162float(h));
}
__device__ __forceinline__ void hsplit(float v, __half& h, __half& l) {
    h = __float2half_rn(v);
    l = __float2half_rn(v - __half2float(h));
}
__device__ __forceinline__ uint32_t pack_bf2(__nv_bfloat16 lo, __nv_bfloat16 hi) {
    __nv_bfloat162 p; p.x = lo; p.y = hi;
    return *(uint32_t*)&p;
}
__device__ __forceinline__ uint32_t pack_h2(__half lo, __half hi) {
    __half2 p; p.x = lo; p.y = hi;
    return *(uint32_t*)&p;
}
__device__ __forceinline__ void cp16(uint32_t saddr, const void* gaddr) {
    asm volatile("cp.async.cg.shared.global [%0], [%1], 16;" :: "r"(saddr), "l"(gaddr));
}
#define CP_COMMIT() asm volatile("cp.async.commit_group;" ::: "memory")
#define CP_WAIT(n)  asm volatile("cp.async.wait_group %0;" :: "n"(n) : "memory")

// ===========================================================================
// Splitters
// ===========================================================================
__global__ void __launch_bounds__(256) split_x(const float* __restrict__ X) {
    int i = blockIdx.x*256 + threadIdx.x;
    float4 v = ((const float4*)X)[i];
    __nv_bfloat16 h[4], l[4];
    bsplit(v.x, h[0], l[0]); bsplit(v.y, h[1], l[1]);
    bsplit(v.z, h[2], l[2]); bsplit(v.w, h[3], l[3]);
    *(uint2*)&g_xh[(size_t)i*4] = *(uint2*)h;
    *(uint2*)&g_xl[(size_t)i*4] = *(uint2*)l;
}

// Transpose: Wqkv -> bf16 hi/lo (which=0); Wout -> fp16 single (which=1)
__global__ void __launch_bounds__(256) split_wT(const float* __restrict__ W, int Nn, int which) {
    __shared__ float sm[32][33];
    const int tx = threadIdx.x, ty = threadIdx.y;
    const int nx = blockIdx.x*32, kx = blockIdx.y*32;
    #pragma unroll
    for (int i = 0; i < 4; i++)
        sm[ty + i*8][tx] = W[(size_t)(kx + ty + i*8)*Nn + nx + tx];
    __syncthreads();
    #pragma unroll
    for (int i = 0; i < 4; i++) {
        float v = sm[tx][ty + i*8];
        size_t o = (size_t)(nx + ty + i*8)*1024 + kx + tx;
        if (which) {
            g_wo16[o] = __float2half_rn(v);
        } else {
            __nv_bfloat16 h, l; bsplit(v, h, l);
            g_wqh[o] = h; g_wql[o] = l;
        }
    }
}

// ===========================================================================
// gemm_qkv: bf16 3-pass, CTA 128x128, 4 warps (2m x 2n) 64x64 warp tile,
// k16 stages, 4-stage cp.async (R15 config).
// ===========================================================================
#define GSTAGE 16384
#define QKV_SMEM (4*GSTAGE)

struct MmaCtx {
    float acc[4][8][4];
    uint32_t sb;
    int offA, offB;
    int wm, wn, lane;
    const char *gAh, *gAl, *gBh, *gBl;
};

__device__ __forceinline__ void mma_init(MmaCtx& c, void* smem,
        const __nv_bfloat16* Ah, const __nv_bfloat16* Al,
        const __nv_bfloat16* Bh, const __nv_bfloat16* Bl,
        int bm, int bn) {
    const int t = threadIdx.x, l = t & 31, w = t >> 5;
    c.lane = l; c.wm = w & 1; c.wn = w >> 1;
    c.sb = smem_u32(smem);
    #pragma unroll
    for (int a = 0; a < 4; a++)
        #pragma unroll
        for (int b = 0; b < 8; b++)
            #pragma unroll
            for (int d = 0; d < 4; d++) c.acc[a][b][d] = 0.f;

    c.gAh = (const char*)(Ah + (size_t)(bm*128 + t)*1024);
    c.gAl = (const char*)(Al + (size_t)(bm*128 + t)*1024);
    c.gBh = (const char*)(Bh + (size_t)(bn*128 + t)*1024);
    c.gBl = (const char*)(Bl + (size_t)(bn*128 + t)*1024);

    const int rowA = c.wm*64 + ((l>>3)&1)*8 + (l&7), kcA = l>>4;
    c.offA = (kcA*128 + rowA)*16;
    const int nB = c.wn*64 + (l&7) + (l>>4)*8, kcB = (l>>3)&1;
    c.offB = (kcB*128 + nB)*16;
}

__device__ __forceinline__ void mma_issue(MmaCtx& c, int j, int slot) {
    const int t = threadIdx.x;
    const uint32_t S = c.sb + slot*GSTAGE;
    const uint32_t d0 = (uint32_t)(t*16), d1 = (uint32_t)((128 + t)*16);
    const size_t go = (size_t)j * 32;
    cp16(S + d0,          c.gAh + go);
    cp16(S + d1,          c.gAh + go + 16);
    cp16(S + 4096 + d0,   c.gAl + go);
    cp16(S + 4096 + d1,   c.gAl + go + 16);
    cp16(S + 8192 + d0,   c.gBh + go);
    cp16(S + 8192 + d1,   c.gBh + go + 16);
    cp16(S + 12288 + d0,  c.gBl + go);
    cp16(S + 12288 + d1,  c.gBl + go + 16);
    CP_COMMIT();
}

__device__ __forceinline__ void mma_compute(MmaCtx& c, int slot) {
    const uint32_t S = c.sb + slot*GSTAGE;
    uint32_t Ah_[4][4], Al_[4][4];
    #pragma unroll
    for (int mt = 0; mt < 4; mt++) {
        ldmx4(Ah_[mt], S + c.offA + mt*256);
        ldmx4(Al_[mt], S + 4096 + c.offA + mt*256);
    }
    #pragma unroll
    for (int ntp = 0; ntp < 4; ntp++) {
        uint32_t bh[4], bl[4];
        ldmx4(bh, S + 8192 + c.offB + ntp*256);
        ldmx4(bl, S + 12288 + c.offB + ntp*256);
        #pragma unroll
        for (int n2 = 0; n2 < 2; n2++) {
            const int nt = ntp*2 + n2;
            #pragma unroll
            for (int mt = 0; mt < 4; mt++) {
                mma_bf16(c.acc[mt][nt], Ah_[mt], bh[n2*2], bh[n2*2+1]);
                mma_bf16(c.acc[mt][nt], Ah_[mt], bl[n2*2], bl[n2*2+1]);
                mma_bf16(c.acc[mt][nt], Al_[mt], bh[n2*2], bh[n2*2+1]);
            }
        }
    }
}

#define MMA_MAIN(c)                                        \
    mma_issue(c, 0, 0); mma_issue(c, 1, 1); mma_issue(c, 2, 2); \
    for (int j = 0; j < 64; j++) {                         \
        CP_WAIT(2);                                        \
        __syncthreads();                                   \
        if (j + 3 < 64) mma_issue(c, j+3, (j+3)&3);        \
        mma_compute(c, j&3);                               \
    }

__global__ void __launch_bounds__(128, 2) gemm_qkv_mma() {
    extern __shared__ __align__(16) char smem[];
    MmaCtx c;
    const int bn = blockIdx.x, bm = blockIdx.y;
    mma_init(c, smem, g_xh, g_xl, g_wqh, g_wql, bm, bn);
    MMA_MAIN(c);

    const int sel = bn >> 3;
    const float sc = (sel == 0) ? 0.03125f * 1.4426950408889634f : 1.0f;
    #pragma unroll
    for (int mt = 0; mt < 4; mt++) {
        const int row0 = bm*128 + c.wm*64 + mt*16 + (c.lane >> 2);
        #pragma unroll
        for (int nt = 0; nt < 8; nt++) {
            const int col = (bn & 7)*128 + c.wn*64 + nt*8 + (c.lane & 3)*2;
            const int h = col >> 6, d = col & 63;
            #pragma unroll
            for (int half = 0; half < 2; half++) {
                const int r = row0 + half*8;
                const int bb = r >> 11, nr = r & 2047;
                const int bh_ = bb*H_ + h;
                float f0 = c.acc[mt][nt][half*2+0]*sc;
                float f1 = c.acc[mt][nt][half*2+1]*sc;
                if (sel == 0) {
                    size_t o = ((size_t)bh_*N_ + nr)*D_ + d;
                    *(uint32_t*)&g_qh2[o] = pack_bf2(__float2bfloat16_rn(f0),
                                                     __float2bfloat16_rn(f1));
                } else if (sel == 1) {
                    __nv_bfloat16 h0,l0,h1,l1;
                    bsplit(f0, h0, l0); bsplit(f1, h1, l1);
                    size_t o = ((size_t)bh_*N_ + nr)*D_ + d;
                    *(uint32_t*)&g_kh2[o] = pack_bf2(h0, h1);
                    *(uint32_t*)&g_kl2[o] = pack_bf2(l0, l1);
                } else {
                    size_t o = ((size_t)bh_*D_ + d)*N_ + nr;
                    g_v16[o]      = __float2half_rn(f0);
                    g_v16[o + N_] = __float2half_rn(f1);
                }
            }
        }
    }
}

// ===========================================================================
// gemm_out: fp16 2-pass (AOh*W16 + AOl*W16). CTA 128x128, 4 warps 64x64,
// k16 stages (12KB: Ah@0 Al@4096 B@8192), 4-stage cp.async.
// ===========================================================================
#define OSTAGE 12288
#define OUT_SMEM (4*OSTAGE)

__global__ void __launch_bounds__(128, 2) gemm_out_mma(const float* __restrict__ bias,
                                                       float* __restrict__ out) {
    extern __shared__ __align__(16) char smem[];
    const int t = threadIdx.x, l = t & 31, w = t >> 5;
    const int wm = w & 1, wn = w >> 1;
    const int bn = blockIdx.x, bm = blockIdx.y;
    const uint32_t sb = smem_u32(smem);

    float acc[4][8][4];
    #pragma unroll
    for (int a = 0; a < 4; a++)
        #pragma unroll
        for (int b = 0; b < 8; b++)
            #pragma unroll
            for (int d = 0; d < 4; d++) acc[a][b][d] = 0.f;

    const char* gAh = (const char*)(g_ao16h + (size_t)(bm*128 + t)*1024);
    const char* gAl = (const char*)(g_ao16l + (size_t)(bm*128 + t)*1024);
    const char* gB  = (const char*)(g_wo16 + (size_t)(bn*128 + t)*1024);

    const int rowA = wm*64 + ((l>>3)&1)*8 + (l&7), kcA = l>>4;
    const int offA = (kcA*128 + rowA)*16;
    const int nB = wn*64 + (l&7) + (l>>4)*8, kcB = (l>>3)&1;
    const int offB = (kcB*128 + nB)*16;

    auto issue = [&](int j, int slot) {
        const uint32_t S = sb + slot*OSTAGE;
        const uint32_t d0 = (uint32_t)(t*16), d1 = (uint32_t)((128 + t)*16);
        const size_t go = (size_t)j * 32;
        cp16(S + d0,         gAh + go);
        cp16(S + d1,         gAh + go + 16);
        cp16(S + 4096 + d0,  gAl + go);
        cp16(S + 4096 + d1,  gAl + go + 16);
        cp16(S + 8192 + d0,  gB + go);
        cp16(S + 8192 + d1,  gB + go + 16);
        CP_COMMIT();
    };
    auto compute = [&](int slot) {
        const uint32_t S = sb + slot*OSTAGE;
        uint32_t Ah_[4][4], Al_[4][4];
        #pragma unroll
        for (int mt = 0; mt < 4; mt++) {
            ldmx4(Ah_[mt], S + offA + mt*256);
            ldmx4(Al_[mt], S + 4096 + offA + mt*256);
        }
        #pragma unroll
        for (int ntp = 0; ntp < 4; ntp++) {
            uint32_t bh[4];
            ldmx4(bh, S + 8192 + offB + ntp*256);
            #pragma unroll
            for (int n2 = 0; n2 < 2; n2++) {
                const int nt = ntp*2 + n2;
                #pragma unroll
                for (int mt = 0; mt < 4; mt++) {
                    mma_f16(acc[mt][nt], Ah_[mt], bh[n2*2], bh[n2*2+1]);
                    mma_f16(acc[mt][nt], Al_[mt], bh[n2*2], bh[n2*2+1]);
                }
            }
        }
    };

    issue(0, 0); issue(1, 1); issue(2, 2);
    for (int j = 0; j < 64; j++) {
        CP_WAIT(2);
        __syncthreads();
        if (j + 3 < 64) issue(j+3, (j+3)&3);
        compute(j&3);
    }

    #pragma unroll
    for (int mt = 0; mt < 4; mt++) {
        const int row0 = bm*128 + wm*64 + mt*16 + (l >> 2);
        #pragma unroll
        for (int nt = 0; nt < 8; nt++) {
            const int col = bn*128 + wn*64 + nt*8 + (l & 3)*2;
            const float2 bv = *(const float2*)&bias[col];
            #pragma unroll
            for (int half = 0; half < 2; half++) {
                const size_t r = (size_t)(row0 + half*8);
                float2 o = make_float2(acc[mt][nt][half*2+0] + bv.x,
                                       acc[mt][nt][half*2+1] + bv.y);
                *(float2*)&out[r*C_ + col] = o;
            }
        }
    }
}

// ===========================================================================
// Attention: S = Qh(bf16, single) x K(hi/lo) 2-pass; PV = P(fp16 hi/lo) x V16
// 2-pass. 256 thr, 8 warps x 16 rows. Q frags hoisted. cp.async dbl-buffer.
// smem: sQ 16KB | stage s @16384+s*24576: Kh 8K, Kl 8K, V16 8K.  = 64KB
// ===========================================================================
#define ATTN_SMEM (16384 + 2*24576)

__global__ void __launch_bounds__(256) attn_mma() {
    extern __shared__ __align__(16) char smem[];
    char* sQ = smem;
    const uint32_t sbQ = smem_u32(sQ);
    const uint32_t sbKV = sbQ + 16384;

    const int t = threadIdx.x, l = t & 31, w = t >> 5;
    const int it = blockIdx.x, bh = blockIdx.y;
    const size_t base = (size_t)bh * (N_*D_);

    // Q tile (bf16 single) -> smem [kcb][row][16B]
    {
        const int row = t & 127;
        const int kcb0 = (t >> 7) * 4;
        const uint4* gh = (const uint4*)(g_qh2 + base + (size_t)(it*128 + row)*D_);
        #pragma unroll
        for (int u = 0; u < 4; u++) {
            const int kcb = kcb0 + u;
            *(uint4*)(sQ + (kcb*128 + row)*16) = gh[kcb];
        }
    }

    const int rowQ = w*16 + ((l>>3)&1)*8 + (l&7);
    const int offQ = rowQ*16 + (l>>4)*2048;
    const int offB = (((l>>3)&1)*64 + (l&7) + (l>>4)*8)*16;

    // K/V loaders
    const int jrow = t & 63;
    const int kcb2 = (t >> 6) * 2;
    const char* gKh = (const char*)(g_kh2 + base + (size_t)jrow*D_) + kcb2*16;
    const char* gKl = (const char*)(g_kl2 + base + (size_t)jrow*D_) + kcb2*16;
    const char* gV  = (const char*)(g_v16 + base + (size_t)jrow*N_) + kcb2*16;
    const uint32_t dK = (uint32_t)((kcb2*64 + jrow)*16);

    auto kv_issue = [&](int jt, int slot) {
        const uint32_t S = sbKV + slot*24576 + dK;
        const size_t koff = (size_t)jt * 64 * D_ * 2;   // K: 64 tok * 64 k * 2B
        const size_t voff = (size_t)jt * 64 * 2;        // V: 64 tok along N_ * 2B
        #pragma unroll
        for (int u = 0; u < 2; u++) {
            cp16(S + u*1024,          gKh + koff + u*16);
            cp16(S + 8192 + u*1024,   gKl + koff + u*16);
            cp16(S + 16384 + u*1024,  gV + voff + u*16);
        }
        CP_COMMIT();
    };

    float oacc[8][4];
    #pragma unroll
    for (int nt = 0; nt < 8; nt++)
        #pragma unroll
        for (int d = 0; d < 4; d++) oacc[nt][d] = 0.f;
    float lrun0 = 0.f, lrun1 = 0.f;

    const int row_glob0 = it*128 + w*16 + (l>>2);

    kv_issue(0, 0);
    __syncthreads();   // Q smem stores visible

    // Hoist Q fragments (jt-invariant)
    uint32_t qf[4][4];
    #pragma unroll
    for (int kc = 0; kc < 4; kc++)
        ldmx4(qf[kc], sbQ + offQ + kc*4096);

    for (int jt = 0; jt < 32; jt++) {
        CP_WAIT(0);
        __syncthreads();
        if (jt + 1 < 32) kv_issue(jt+1, (jt+1)&1);

        const uint32_t sbK = sbKV + (jt&1)*24576;
        const uint32_t sbV = sbK + 16384;

        // S = Q K^T  (2-pass: qh*kh + qh*kl)
        float sacc[8][4];
        #pragma unroll
        for (int nt = 0; nt < 8; nt++)
            #pragma unroll
            for (int d = 0; d < 4; d++) sacc[nt][d] = 0.f;

        #pragma unroll
        for (int kc = 0; kc < 4; kc++) {
            #pragma unroll
            for (int np = 0; np < 4; np++) {
                uint32_t kbh[4], kbl[4];
                ldmx4(kbh, sbK + kc*2048 + offB + np*256);
                ldmx4(kbl, sbK + 8192 + kc*2048 + offB + np*256);
                #pragma unroll
                for (int n2 = 0; n2 < 2; n2++) {
                    const int nt = np*2 + n2;
                    mma_bf16(sacc[nt], qf[kc], kbh[n2*2], kbh[n2*2+1]);
                    mma_bf16(sacc[nt], qf[kc], kbl[n2*2], kbl[n2*2+1]);
                }
            }
        }

        // mask + exp2 + partial sums + pack P into fp16 a-frags
        uint32_t pah[4][4], pal[4][4];
        #pragma unroll
        for (int nt = 0; nt < 8; nt++) {
            const int colb = jt*64 + nt*8 + (l & 3)*2;
            const int del0 = row_glob0 - colb;
            const int dels[4] = {del0, del0 - 1, del0 + 8, del0 + 7};
            float p[4];
            #pragma unroll
            for (int e = 0; e < 4; e++) {
                const int de = dels[e];
                const bool msk = (de >= 0) && ((de & 31) == 0);
                p[e] = msk ? 0.f : exp2f(sacc[nt][e]);
            }
            lrun0 += p[0] + p[1];
            lrun1 += p[2] + p[3];
            __half h0,l0,h1,l1,h2,l2,h3,l3;
            hsplit(p[0], h0, l0); hsplit(p[1], h1, l1);
            hsplit(p[2], h2, l2); hsplit(p[3], h3, l3);
            const int kk = nt >> 1, sl = (nt & 1)*2;
            pah[kk][sl+0] = pack_h2(h0, h1);
            pah[kk][sl+1] = pack_h2(h2, h3);
            pal[kk][sl+0] = pack_h2(l0, l1);
            pal[kk][sl+1] = pack_h2(l2, l3);
        }

        // O += P V  (2-pass: ph*v16 + pl*v16)
        #pragma unroll
        for (int kk = 0; kk < 4; kk++) {
            #pragma unroll
            for (int np = 0; np < 4; np++) {
                uint32_t vb[4];
                ldmx4(vb, sbV + kk*2048 + offB + np*256);
                #pragma unroll
                for (int n2 = 0; n2 < 2; n2++) {
                    const int nt = np*2 + n2;
                    mma_f16(oacc[nt], pah[kk], vb[n2*2], vb[n2*2+1]);
                    mma_f16(oacc[nt], pal[kk], vb[n2*2], vb[n2*2+1]);
                }
            }
        }
    }

    // final reduce + normalize + fp16 split store
    lrun0 += __shfl_xor_sync(0xffffffffu, lrun0, 1);
    lrun0 += __shfl_xor_sync(0xffffffffu, lrun0, 2);
    lrun1 += __shfl_xor_sync(0xffffffffu, lrun1, 1);
    lrun1 += __shfl_xor_sync(0xffffffffu, lrun1, 2);
    const float inv0 = 1.0f / lrun0, inv1 = 1.0f / lrun1;

    const int bb = bh >> 4, hh_ = bh & 15;
    #pragma unroll
    for (int nt = 0; nt < 8; nt++) {
        const int col = hh_*64 + nt*8 + (l & 3)*2;
        #pragma unroll
        for (int half = 0; half < 2; half++) {
            const float inv = half ? inv1 : inv0;
            float f0 = oacc[nt][half*2+0] * inv;
            float f1 = oacc[nt][half*2+1] * inv;
            __half h0,l0,h1,l1;
            hsplit(f0, h0, l0); hsplit(f1, h1, l1);
            const int gi = it*128 + w*16 + (l>>2) + half*8;
            const size_t o = ((size_t)bb*N_ + gi)*C_ + col;
            *(uint32_t*)&g_ao16h[o] = pack_h2(h0, h1);
            *(uint32_t*)&g_ao16l[o] = pack_h2(l0, l1);
        }
    }
}

extern "C" void kernel_launch(void* const* d_in, const int* in_sizes, int n_in,
                              void* d_out, int out_size) {
    const float* x    = (const float*)d_in[0];
    const float* Wqkv = (const float*)d_in[1];
    const float* Wout = (const float*)d_in[2];
    const float* bout = (const float*)d_in[3];
    float* out = (float*)d_out;

    cudaFuncSetAttribute(gemm_qkv_mma, cudaFuncAttributeMaxDynamicSharedMemorySize, QKV_SMEM);
    cudaFuncSetAttribute(gemm_out_mma, cudaFuncAttributeMaxDynamicSharedMemorySize, OUT_SMEM);
    cudaFuncSetAttribute(attn_mma, cudaFuncAttributeMaxDynamicSharedMemorySize, ATTN_SMEM);

    split_x<<<4096, 256>>>(x);
    split_wT<<<dim3(96, 32), dim3(32, 8)>>>(Wqkv, 3072, 0);
    split_wT<<<dim3(32, 32), dim3(32, 8)>>>(Wout, 1024, 1);
    gemm_qkv_mma<<<dim3(24, 32), 128, QKV_SMEM>>>();
    attn_mma<<<dim3(16, 32), 256, ATTN_SMEM>>>();
    gemm_out_mma<<<dim3(8, 32), 128, OUT_SMEM>>>(bout, out);
}

// round 17
// speedup vs baseline: 1.4654x; 1.0647x over previous
#include <cuda_runtime.h>
#include <cuda_bf16.h>
#include <cuda_fp16.h>
#include <cstdint>
#include <math.h>

#define B_   2
#define H_   16
#define N_   2048
#define D_   64
#define C_   1024
#define BH_  (B_*H_)

// scratch
__device__ __nv_bfloat16 g_xh[4096*1024], g_xl[4096*1024];     // X split (bf16 hi/lo)
__device__ __nv_bfloat16 g_wqh[3072*1024], g_wql[3072*1024];   // Wqkv^T split (bf16 hi/lo)
__device__ __half        g_wo16[1024*1024];                    // Wout^T (fp16)
__device__ __half        g_ao16[4096*1024];                    // attn out (fp16 single)
__device__ __nv_bfloat16 g_qh2[BH_*N_*D_];                     // Q (bf16 single), *log2e/32
__device__ __nv_bfloat16 g_kh2[BH_*N_*D_], g_kl2[BH_*N_*D_];   // K (bf16 hi/lo)
__device__ __half        g_v16[BH_*N_*D_];                     // V^T [bh][d][tok] (fp16)

// ---- helpers ----
__device__ __forceinline__ uint32_t smem_u32(const void* p) {
    uint32_t a;
    asm("{ .reg .u64 t; cvta.to.shared.u64 t, %1; cvt.u32.u64 %0, t; }" : "=r"(a) : "l"(p));
    return a;
}
__device__ __forceinline__ void ldmx4(uint32_t* r, uint32_t addr) {
    asm volatile("ldmatrix.sync.aligned.m8n8.x4.shared.b16 {%0,%1,%2,%3}, [%4];"
                 : "=r"(r[0]), "=r"(r[1]), "=r"(r[2]), "=r"(r[3]) : "r"(addr));
}
__device__ __forceinline__ void mma_bf16(float* d, const uint32_t* a, uint32_t b0, uint32_t b1) {
    asm volatile("mma.sync.aligned.m16n8k16.row.col.f32.bf16.bf16.f32 "
                 "{%0,%1,%2,%3}, {%4,%5,%6,%7}, {%8,%9}, {%0,%1,%2,%3};"
                 : "+f"(d[0]), "+f"(d[1]), "+f"(d[2]), "+f"(d[3])
                 : "r"(a[0]), "r"(a[1]), "r"(a[2]), "r"(a[3]), "r"(b0), "r"(b1));
}
__device__ __forceinline__ void mma_f16(float* d, const uint32_t* a, uint32_t b0, uint32_t b1) {
    asm volatile("mma.sync.aligned.m16n8k16.row.col.f32.f16.f16.f32 "
                 "{%0,%1,%2,%3}, {%4,%5,%6,%7}, {%8,%9}, {%0,%1,%2,%3};"
                 : "+f"(d[0]), "+f"(d[1]), "+f"(d[2]), "+f"(d[3])
                 : "r"(a[0]), "r"(a[1]), "r"(a[2]), "r"(a[3]), "r"(b0), "r"(b1));
}
__device__ __forceinline__ void bsplit(float v, __nv_bfloat16& h, __nv_bfloat16& l) {
    h = __float2bfloat16_rn(v);
    l = __float2bfloat16_rn(v - __bfloat162float(h));
}
__device__ __forceinline__ uint32_t pack_bf2(__nv_bfloat16 lo, __nv_bfloat16 hi) {
    __nv_bfloat162 p; p.x = lo; p.y = hi;
    return *(uint32_t*)&p;
}
__device__ __forceinline__ uint32_t pack_h2(__half lo, __half hi) {
    __half2 p; p.x = lo; p.y = hi;
    return *(uint32_t*)&p;
}
__device__ __forceinline__ void cp16(uint32_t saddr, const void* gaddr) {
    asm volatile("cp.async.cg.shared.global [%0], [%1], 16;" :: "r"(saddr), "l"(gaddr));
}
#define CP_COMMIT() asm volatile("cp.async.commit_group;" ::: "memory")
#define CP_WAIT(n)  asm volatile("cp.async.wait_group %0;" :: "n"(n) : "memory")

// ===========================================================================
// Splitters
// ===========================================================================
__global__ void __launch_bounds__(256) split_x(const float* __restrict__ X) {
    int i = blockIdx.x*256 + threadIdx.x;
    float4 v = ((const float4*)X)[i];
    __nv_bfloat16 h[4], l[4];
    bsplit(v.x, h[0], l[0]); bsplit(v.y, h[1], l[1]);
    bsplit(v.z, h[2], l[2]); bsplit(v.w, h[3], l[3]);
    *(uint2*)&g_xh[(size_t)i*4] = *(uint2*)h;
    *(uint2*)&g_xl[(size_t)i*4] = *(uint2*)l;
}

__global__ void __launch_bounds__(256) split_wT(const float* __restrict__ W, int Nn, int which) {
    __shared__ float sm[32][33];
    const int tx = threadIdx.x, ty = threadIdx.y;
    const int nx = blockIdx.x*32, kx = blockIdx.y*32;
    #pragma unroll
    for (int i = 0; i < 4; i++)
        sm[ty + i*8][tx] = W[(size_t)(kx + ty + i*8)*Nn + nx + tx];
    __syncthreads();
    #pragma unroll
    for (int i = 0; i < 4; i++) {
        float v = sm[tx][ty + i*8];
        size_t o = (size_t)(nx + ty + i*8)*1024 + kx + tx;
        if (which) {
            g_wo16[o] = __float2half_rn(v);
        } else {
            __nv_bfloat16 h, l; bsplit(v, h, l);
            g_wqh[o] = h; g_wql[o] = l;
        }
    }
}

// ===========================================================================
// gemm_qkv: bf16 3-pass (2-pass for Q CTAs), CTA 128x128, 4 warps 64x64,
// k16 stages, 4-stage cp.async.
// ===========================================================================
#define GSTAGE 16384
#define QKV_SMEM (4*GSTAGE)

struct MmaCtx {
    float acc[4][8][4];
    uint32_t sb;
    int offA, offB;
    int wm, wn, lane;
    const char *gAh, *gAl, *gBh, *gBl;
};

__device__ __forceinline__ void mma_init(MmaCtx& c, void* smem,
        const __nv_bfloat16* Ah, const __nv_bfloat16* Al,
        const __nv_bfloat16* Bh, const __nv_bfloat16* Bl,
        int bm, int bn) {
    const int t = threadIdx.x, l = t & 31, w = t >> 5;
    c.lane = l; c.wm = w & 1; c.wn = w >> 1;
    c.sb = smem_u32(smem);
    #pragma unroll
    for (int a = 0; a < 4; a++)
        #pragma unroll
        for (int b = 0; b < 8; b++)
            #pragma unroll
            for (int d = 0; d < 4; d++) c.acc[a][b][d] = 0.f;

    c.gAh = (const char*)(Ah + (size_t)(bm*128 + t)*1024);
    c.gAl = (const char*)(Al + (size_t)(bm*128 + t)*1024);
    c.gBh = (const char*)(Bh + (size_t)(bn*128 + t)*1024);
    c.gBl = (const char*)(Bl + (size_t)(bn*128 + t)*1024);

    const int rowA = c.wm*64 + ((l>>3)&1)*8 + (l&7), kcA = l>>4;
    c.offA = (kcA*128 + rowA)*16;
    const int nB = c.wn*64 + (l&7) + (l>>4)*8, kcB = (l>>3)&1;
    c.offB = (kcB*128 + nB)*16;
}

__device__ __forceinline__ void mma_issue(MmaCtx& c, int j, int slot) {
    const int t = threadIdx.x;
    const uint32_t S = c.sb + slot*GSTAGE;
    const uint32_t d0 = (uint32_t)(t*16), d1 = (uint32_t)((128 + t)*16);
    const size_t go = (size_t)j * 32;
    cp16(S + d0,          c.gAh + go);
    cp16(S + d1,          c.gAh + go + 16);
    cp16(S + 4096 + d0,   c.gAl + go);
    cp16(S + 4096 + d1,   c.gAl + go + 16);
    cp16(S + 8192 + d0,   c.gBh + go);
    cp16(S + 8192 + d1,   c.gBh + go + 16);
    cp16(S + 12288 + d0,  c.gBl + go);
    cp16(S + 12288 + d1,  c.gBl + go + 16);
    CP_COMMIT();
}

__device__ __forceinline__ void mma_compute(MmaCtx& c, int slot, bool threep) {
    const uint32_t S = c.sb + slot*GSTAGE;
    uint32_t Ah_[4][4], Al_[4][4];
    #pragma unroll
    for (int mt = 0; mt < 4; mt++) {
        ldmx4(Ah_[mt], S + c.offA + mt*256);
        if (threep) ldmx4(Al_[mt], S + 4096 + c.offA + mt*256);
    }
    #pragma unroll
    for (int ntp = 0; ntp < 4; ntp++) {
        uint32_t bh[4], bl[4];
        ldmx4(bh, S + 8192 + c.offB + ntp*256);
        ldmx4(bl, S + 12288 + c.offB + ntp*256);
        #pragma unroll
        for (int n2 = 0; n2 < 2; n2++) {
            const int nt = ntp*2 + n2;
            #pragma unroll
            for (int mt = 0; mt < 4; mt++) {
                mma_bf16(c.acc[mt][nt], Ah_[mt], bh[n2*2], bh[n2*2+1]);
                mma_bf16(c.acc[mt][nt], Ah_[mt], bl[n2*2], bl[n2*2+1]);
                if (threep) mma_bf16(c.acc[mt][nt], Al_[mt], bh[n2*2], bh[n2*2+1]);
            }
        }
    }
}

#define MMA_MAIN(c, threep)                                \
    mma_issue(c, 0, 0); mma_issue(c, 1, 1); mma_issue(c, 2, 2); \
    for (int j = 0; j < 64; j++) {                         \
        CP_WAIT(2);                                        \
        __syncthreads();                                   \
        if (j + 3 < 64) mma_issue(c, j+3, (j+3)&3);        \
        mma_compute(c, j&3, threep);                       \
    }

__global__ void __launch_bounds__(128, 2) gemm_qkv_mma() {
    extern __shared__ __align__(16) char smem[];
    MmaCtx c;
    const int bn = blockIdx.x, bm = blockIdx.y;
    const int sel = bn >> 3;
    mma_init(c, smem, g_xh, g_xl, g_wqh, g_wql, bm, bn);
    const bool threep = (sel != 0);   // Q output is rounded to single bf16 anyway
    MMA_MAIN(c, threep);

    const float sc = (sel == 0) ? 0.03125f * 1.4426950408889634f : 1.0f;
    #pragma unroll
    for (int mt = 0; mt < 4; mt++) {
        const int row0 = bm*128 + c.wm*64 + mt*16 + (c.lane >> 2);
        #pragma unroll
        for (int nt = 0; nt < 8; nt++) {
            const int col = (bn & 7)*128 + c.wn*64 + nt*8 + (c.lane & 3)*2;
            const int h = col >> 6, d = col & 63;
            #pragma unroll
            for (int half = 0; half < 2; half++) {
                const int r = row0 + half*8;
                const int bb = r >> 11, nr = r & 2047;
                const int bh_ = bb*H_ + h;
                float f0 = c.acc[mt][nt][half*2+0]*sc;
                float f1 = c.acc[mt][nt][half*2+1]*sc;
                if (sel == 0) {
                    size_t o = ((size_t)bh_*N_ + nr)*D_ + d;
                    *(uint32_t*)&g_qh2[o] = pack_bf2(__float2bfloat16_rn(f0),
                                                     __float2bfloat16_rn(f1));
                } else if (sel == 1) {
                    __nv_bfloat16 h0,l0,h1,l1;
                    bsplit(f0, h0, l0); bsplit(f1, h1, l1);
                    size_t o = ((size_t)bh_*N_ + nr)*D_ + d;
                    *(uint32_t*)&g_kh2[o] = pack_bf2(h0, h1);
                    *(uint32_t*)&g_kl2[o] = pack_bf2(l0, l1);
                } else {
                    size_t o = ((size_t)bh_*D_ + d)*N_ + nr;
                    g_v16[o]      = __float2half_rn(f0);
                    g_v16[o + N_] = __float2half_rn(f1);
                }
            }
        }
    }
}

// ===========================================================================
// gemm_out: fp16 1-pass (AO16 * W16). CTA 128x128, 4 warps 64x64,
// k16 stages (8KB: A@0 B@4096), 4-stage cp.async.
// ===========================================================================
#define OSTAGE 8192
#define OUT_SMEM (4*OSTAGE)

__global__ void __launch_bounds__(128, 2) gemm_out_mma(const float* __restrict__ bias,
                                                       float* __restrict__ out) {
    extern __shared__ __align__(16) char smem[];
    const int t = threadIdx.x, l = t & 31, w = t >> 5;
    const int wm = w & 1, wn = w >> 1;
    const int bn = blockIdx.x, bm = blockIdx.y;
    const uint32_t sb = smem_u32(smem);

    float acc[4][8][4];
    #pragma unroll
    for (int a = 0; a < 4; a++)
        #pragma unroll
        for (int b = 0; b < 8; b++)
            #pragma unroll
            for (int d = 0; d < 4; d++) acc[a][b][d] = 0.f;

    const char* gA = (const char*)(g_ao16 + (size_t)(bm*128 + t)*1024);
    const char* gB = (const char*)(g_wo16 + (size_t)(bn*128 + t)*1024);

    const int rowA = wm*64 + ((l>>3)&1)*8 + (l&7), kcA = l>>4;
    const int offA = (kcA*128 + rowA)*16;
    const int nB = wn*64 + (l&7) + (l>>4)*8, kcB = (l>>3)&1;
    const int offB = (kcB*128 + nB)*16;

    auto issue = [&](int j, int slot) {
        const uint32_t S = sb + slot*OSTAGE;
        const uint32_t d0 = (uint32_t)(t*16), d1 = (uint32_t)((128 + t)*16);
        const size_t go = (size_t)j * 32;
        cp16(S + d0,         gA + go);
        cp16(S + d1,         gA + go + 16);
        cp16(S + 4096 + d0,  gB + go);
        cp16(S + 4096 + d1,  gB + go + 16);
        CP_COMMIT();
    };
    auto compute = [&](int slot) {
        const uint32_t S = sb + slot*OSTAGE;
        uint32_t Ah_[4][4];
        #pragma unroll
        for (int mt = 0; mt < 4; mt++)
            ldmx4(Ah_[mt], S + offA + mt*256);
        #pragma unroll
        for (int ntp = 0; ntp < 4; ntp++) {
            uint32_t bh[4];
            ldmx4(bh, S + 4096 + offB + ntp*256);
            #pragma unroll
            for (int n2 = 0; n2 < 2; n2++) {
                const int nt = ntp*2 + n2;
                #pragma unroll
                for (int mt = 0; mt < 4; mt++)
                    mma_f16(acc[mt][nt], Ah_[mt], bh[n2*2], bh[n2*2+1]);
            }
        }
    };

    issue(0, 0); issue(1, 1); issue(2, 2);
    for (int j = 0; j < 64; j++) {
        CP_WAIT(2);
        __syncthreads();
        if (j + 3 < 64) issue(j+3, (j+3)&3);
        compute(j&3);
    }

    #pragma unroll
    for (int mt = 0; mt < 4; mt++) {
        const int row0 = bm*128 + wm*64 + mt*16 + (l >> 2);
        #pragma unroll
        for (int nt = 0; nt < 8; nt++) {
            const int col = bn*128 + wn*64 + nt*8 + (l & 3)*2;
            const float2 bv = *(const float2*)&bias[col];
            #pragma unroll
            for (int half = 0; half < 2; half++) {
                const size_t r = (size_t)(row0 + half*8);
                float2 o = make_float2(acc[mt][nt][half*2+0] + bv.x,
                                       acc[mt][nt][half*2+1] + bv.y);
                *(float2*)&out[r*C_ + col] = o;
            }
        }
    }
}

// ===========================================================================
// Attention: S = Q(bf16 single) x K(hi/lo) 2-pass bf16; PV = P(fp16 single)
// x V16 1-pass. 256 thr, 8 warps x 16 rows. Q frags hoisted.
// smem: sQ 16KB | stage s @16384+s*24576: Kh 8K, Kl 8K, V16 8K.
// ===========================================================================
#define ATTN_SMEM (16384 + 2*24576)

__global__ void __launch_bounds__(256) attn_mma() {
    extern __shared__ __align__(16) char smem[];
    char* sQ = smem;
    const uint32_t sbQ = smem_u32(sQ);
    const uint32_t sbKV = sbQ + 16384;

    const int t = threadIdx.x, l = t & 31, w = t >> 5;
    const int it = blockIdx.x, bh = blockIdx.y;
    const size_t base = (size_t)bh * (N_*D_);

    {
        const int row = t & 127;
        const int kcb0 = (t >> 7) * 4;
        const uint4* gh = (const uint4*)(g_qh2 + base + (size_t)(it*128 + row)*D_);
        #pragma unroll
        for (int u = 0; u < 4; u++) {
            const int kcb = kcb0 + u;
            *(uint4*)(sQ + (kcb*128 + row)*16) = gh[kcb];
        }
    }

    const int rowQ = w*16 + ((l>>3)&1)*8 + (l&7);
    const int offQ = rowQ*16 + (l>>4)*2048;
    const int offB = (((l>>3)&1)*64 + (l&7) + (l>>4)*8)*16;

    const int jrow = t & 63;
    const int kcb2 = (t >> 6) * 2;
    const char* gKh = (const char*)(g_kh2 + base + (size_t)jrow*D_) + kcb2*16;
    const char* gKl = (const char*)(g_kl2 + base + (size_t)jrow*D_) + kcb2*16;
    const char* gV  = (const char*)(g_v16 + base + (size_t)jrow*N_) + kcb2*16;
    const uint32_t dK = (uint32_t)((kcb2*64 + jrow)*16);

    auto kv_issue = [&](int jt, int slot) {
        const uint32_t S = sbKV + slot*24576 + dK;
        const size_t koff = (size_t)jt * 64 * D_ * 2;
        const size_t voff = (size_t)jt * 64 * 2;
        #pragma unroll
        for (int u = 0; u < 2; u++) {
            cp16(S + u*1024,          gKh + koff + u*16);
            cp16(S + 8192 + u*1024,   gKl + koff + u*16);
            cp16(S + 16384 + u*1024,  gV + voff + u*16);
        }
        CP_COMMIT();
    };

    float oacc[8][4];
    #pragma unroll
    for (int nt = 0; nt < 8; nt++)
        #pragma unroll
        for (int d = 0; d < 4; d++) oacc[nt][d] = 0.f;
    float lrun0 = 0.f, lrun1 = 0.f;

    const int row_glob0 = it*128 + w*16 + (l>>2);

    kv_issue(0, 0);
    __syncthreads();

    uint32_t qf[4][4];
    #pragma unroll
    for (int kc = 0; kc < 4; kc++)
        ldmx4(qf[kc], sbQ + offQ + kc*4096);

    for (int jt = 0; jt < 32; jt++) {
        CP_WAIT(0);
        __syncthreads();
        if (jt + 1 < 32) kv_issue(jt+1, (jt+1)&1);

        const uint32_t sbK = sbKV + (jt&1)*24576;
        const uint32_t sbV = sbK + 16384;

        // S = Q K^T  (2-pass)
        float sacc[8][4];
        #pragma unroll
        for (int nt = 0; nt < 8; nt++)
            #pragma unroll
            for (int d = 0; d < 4; d++) sacc[nt][d] = 0.f;

        #pragma unroll
        for (int kc = 0; kc < 4; kc++) {
            #pragma unroll
            for (int np = 0; np < 4; np++) {
                uint32_t kbh[4], kbl[4];
                ldmx4(kbh, sbK + kc*2048 + offB + np*256);
                ldmx4(kbl, sbK + 8192 + kc*2048 + offB + np*256);
                #pragma unroll
                for (int n2 = 0; n2 < 2; n2++) {
                    const int nt = np*2 + n2;
                    mma_bf16(sacc[nt], qf[kc], kbh[n2*2], kbh[n2*2+1]);
                    mma_bf16(sacc[nt], qf[kc], kbl[n2*2], kbl[n2*2+1]);
                }
            }
        }

        // mask + exp2 + partial sums + pack P (single fp16)
        uint32_t pah[4][4];
        #pragma unroll
        for (int nt = 0; nt < 8; nt++) {
            const int colb = jt*64 + nt*8 + (l & 3)*2;
            const int del0 = row_glob0 - colb;
            const int dels[4] = {del0, del0 - 1, del0 + 8, del0 + 7};
            float p[4];
            #pragma unroll
            for (int e = 0; e < 4; e++) {
                const int de = dels[e];
                const bool msk = (de >= 0) && ((de & 31) == 0);
                p[e] = msk ? 0.f : exp2f(sacc[nt][e]);
            }
            lrun0 += p[0] + p[1];
            lrun1 += p[2] + p[3];
            const int kk = nt >> 1, sl = (nt & 1)*2;
            pah[kk][sl+0] = pack_h2(__float2half_rn(p[0]), __float2half_rn(p[1]));
            pah[kk][sl+1] = pack_h2(__float2half_rn(p[2]), __float2half_rn(p[3]));
        }

        // O += P V  (1-pass)
        #pragma unroll
        for (int kk = 0; kk < 4; kk++) {
            #pragma unroll
            for (int np = 0; np < 4; np++) {
                uint32_t vb[4];
                ldmx4(vb, sbV + kk*2048 + offB + np*256);
                #pragma unroll
                for (int n2 = 0; n2 < 2; n2++) {
                    const int nt = np*2 + n2;
                    mma_f16(oacc[nt], pah[kk], vb[n2*2], vb[n2*2+1]);
                }
            }
        }
    }

    lrun0 += __shfl_xor_sync(0xffffffffu, lrun0, 1);
    lrun0 += __shfl_xor_sync(0xffffffffu, lrun0, 2);
    lrun1 += __shfl_xor_sync(0xffffffffu, lrun1, 1);
    lrun1 += __shfl_xor_sync(0xffffffffu, lrun1, 2);
    const float inv0 = 1.0f / lrun0, inv1 = 1.0f / lrun1;

    const int bb = bh >> 4, hh_ = bh & 15;
    #pragma unroll
    for (int nt = 0; nt < 8; nt++) {
        const int col = hh_*64 + nt*8 + (l & 3)*2;
        #pragma unroll
        for (int half = 0; half < 2; half++) {
            const float inv = half ? inv1 : inv0;
            float f0 = oacc[nt][half*2+0] * inv;
            float f1 = oacc[nt][half*2+1] * inv;
            const int gi = it*128 + w*16 + (l>>2) + half*8;
            const size_t o = ((size_t)bb*N_ + gi)*C_ + col;
            *(uint32_t*)&g_ao16[o] = pack_h2(__float2half_rn(f0), __float2half_rn(f1));
        }
    }
}

extern "C" void kernel_launch(void* const* d_in, const int* in_sizes, int n_in,
                              void* d_out, int out_size) {
    const float* x    = (const float*)d_in[0];
    const float* Wqkv = (const float*)d_in[1];
    const float* Wout = (const float*)d_in[2];
    const float* bout = (const float*)d_in[3];
    float* out = (float*)d_out;

    cudaFuncSetAttribute(gemm_qkv_mma, cudaFuncAttributeMaxDynamicSharedMemorySize, QKV_SMEM);
    cudaFuncSetAttribute(gemm_out_mma, cudaFuncAttributeMaxDynamicSharedMemorySize, OUT_SMEM);
    cudaFuncSetAttribute(attn_mma, cudaFuncAttributeMaxDynamicSharedMemorySize, ATTN_SMEM);

    split_x<<<4096, 256>>>(x);
    split_wT<<<dim3(96, 32), dim3(32, 8)>>>(Wqkv, 3072, 0);
    split_wT<<<dim3(32, 32), dim3(32, 8)>>>(Wout, 1024, 1);
    gemm_qkv_mma<<<dim3(24, 32), 128, QKV_SMEM>>>();
    attn_mma<<<dim3(16, 32), 256, ATTN_SMEM>>>();
    gemm_out_mma<<<dim3(8, 32), 128, OUT_SMEM>>>(bout, out);
}